// round 14
// baseline (speedup 1.0000x reference)
#include <cuda_runtime.h>
#include <cuda_bf16.h>
#include <cstdint>

namespace {
constexpr int B   = 8;
constexpr int H   = 97;
constexpr int W   = 97;
constexpr int C   = 512;
constexpr int P   = H * W;        // 9409
constexpr int S   = H + W;        // 194
constexpr int BP  = B * P;        // 75272
constexpr int KA  = 2 * C;        // 1024: [hi | lo] storage
constexpr int NCH = 16;           // proj: 16 physical chunks of k32
constexpr int MBLK = (BP + 127) / 128;   // 589
constexpr int SP   = 224;         // padded attention row stride (bf16)
constexpr int OFFW = 112;         // aW section offset within SP
constexpr int TILE_E = 128 * 40;  // proj smem tile elems
constexpr int SMEM_PROJ = 8 * TILE_E * 2;     // 81920 bytes
constexpr int SC_TE = 128 * 72;               // score tile elems
constexpr int SMEM_SCORE = 4 * SC_TE * 2;     // 73728 bytes
// apply (round-12 shape): A tiles 128x40, V tiles 32x136, 2 stages, hi+lo
constexpr int APT = 128 * 40;
constexpr int VPT = 32 * 136;
constexpr int SMEM_APPLY = (4 * APT + 4 * VPT) * 2;   // 75776 bytes
constexpr float NEG_INF = -1000000000.0f;
}

// ---------------- scratch ---------------------------------------------------
__device__ float g_xT[BP * C];
__device__ float g_yT[BP * C];
__device__ float g_s [BP * S];
__device__ __nv_bfloat16 g_qkh[(long)BP * 128];
__device__ __nv_bfloat16 g_qkl[(long)BP * 128];
__device__ __nv_bfloat16 g_sh[(long)BP * SP];
__device__ __nv_bfloat16 g_sl[(long)BP * SP];
__device__ __nv_bfloat16 g_vh[(long)BP * C];
__device__ __nv_bfloat16 g_vl[(long)BP * C];
__device__ __nv_bfloat16 g_xs[(long)BP * KA];     // split x: [hi | lo]
__device__ __nv_bfloat16 g_wsv [C * KA];
__device__ __nv_bfloat16 g_wsqk[128 * KA];
__device__ float g_bqk[128];

__device__ __forceinline__ uint32_t smem_u32(const void* p) {
    uint32_t a;
    asm("{ .reg .u64 t; cvta.to.shared.u64 t, %1; cvt.u32.u64 %0, t; }" : "=r"(a) : "l"(p));
    return a;
}
__device__ __forceinline__ void cp16(uint32_t dst, const void* src, bool valid) {
    int sz = valid ? 16 : 0;
    asm volatile("cp.async.cg.shared.global [%0], [%1], 16, %2;" :: "r"(dst), "l"(src), "r"(sz));
}
__device__ __forceinline__ void cp16v(uint32_t dst, const void* src, int bytes) {
    asm volatile("cp.async.cg.shared.global [%0], [%1], 16, %2;" :: "r"(dst), "l"(src), "r"(bytes));
}
#define CP_COMMIT() asm volatile("cp.async.commit_group;" ::: "memory")
#define CP_WAIT(n)  asm volatile("cp.async.wait_group %0;" :: "n"(n) : "memory")

// ---------------- transpose in: (B,C,P) -> split bf16 only -------------------
__global__ void transpose_in(const float* __restrict__ src, __nv_bfloat16* __restrict__ xs) {
    __shared__ float t[32][33];
    int b = blockIdx.z, n0 = blockIdx.x * 32, c0 = blockIdx.y * 32;
    const float* sp = src + (long)b * C * P;
    for (int i = threadIdx.y; i < 32; i += 8) {
        int n = n0 + threadIdx.x;
        if (n < P) t[i][threadIdx.x] = sp[(long)(c0 + i) * P + n];
    }
    __syncthreads();
    for (int i = threadIdx.y; i < 32; i += 8) {
        int n = n0 + i;
        if (n < P) {
            float v = t[threadIdx.x][i];
            long m = (long)b * P + n;
            __nv_bfloat16 hv = __float2bfloat16(v);
            xs[m * KA + c0 + threadIdx.x]     = hv;
            xs[m * KA + C + c0 + threadIdx.x] = __float2bfloat16(v - __bfloat162float(hv));
        }
    }
}
__global__ void transpose_out(const float* __restrict__ src, float* __restrict__ dst) {
    __shared__ float t[32][33];
    int b = blockIdx.z, n0 = blockIdx.x * 32, c0 = blockIdx.y * 32;
    const float* sp = src + (long)b * P * C;
    float*       dp = dst + (long)b * C * P;
    for (int i = threadIdx.y; i < 32; i += 8) {
        int n = n0 + i;
        if (n < P) t[i][threadIdx.x] = sp[(long)n * C + c0 + threadIdx.x];
    }
    __syncthreads();
    for (int i = threadIdx.y; i < 32; i += 8) {
        int n = n0 + threadIdx.x;
        if (n < P) dp[(long)(c0 + i) * P + n] = t[threadIdx.x][i];
    }
}

__global__ __launch_bounds__(256) void prep_w(const float* __restrict__ Wq, const float* __restrict__ Wk,
                                              const float* __restrict__ Wv, const float* __restrict__ bq,
                                              const float* __restrict__ bk) {
    int i = blockIdx.x * 256 + threadIdx.x;
    if (blockIdx.x == 0 && threadIdx.x < 128)
        g_bqk[threadIdx.x] = threadIdx.x < 64 ? bq[threadIdx.x] : bk[threadIdx.x - 64];
    if (i >= 640 * 128) return;
    int r = i >> 7, c4 = (i & 127) * 4;
    const float* src; __nv_bfloat16* dst;
    if (r < 512) { src = Wv + (long)r * C + c4; dst = g_wsv + (long)r * KA; }
    else {
        int rr = r - 512;
        src = (rr < 64 ? Wq + (long)rr * C : Wk + (long)(rr - 64) * C) + c4;
        dst = g_wsqk + (long)rr * KA;
    }
    float4 x = *(const float4*)src;
    __nv_bfloat16 h0 = __float2bfloat16(x.x), h1 = __float2bfloat16(x.y);
    __nv_bfloat16 h2 = __float2bfloat16(x.z), h3 = __float2bfloat16(x.w);
    __nv_bfloat16 l0 = __float2bfloat16(x.x - __bfloat162float(h0));
    __nv_bfloat16 l1 = __float2bfloat16(x.y - __bfloat162float(h1));
    __nv_bfloat16 l2 = __float2bfloat16(x.z - __bfloat162float(h2));
    __nv_bfloat16 l3 = __float2bfloat16(x.w - __bfloat162float(h3));
    __nv_bfloat162 H01; H01.x = h0; H01.y = h1;
    __nv_bfloat162 H23; H23.x = h2; H23.y = h3;
    __nv_bfloat162 L01; L01.x = l0; L01.y = l1;
    __nv_bfloat162 L23; L23.x = l2; L23.y = l3;
    *(__nv_bfloat162*)&dst[c4]         = H01; *(__nv_bfloat162*)&dst[c4 + 2]     = H23;
    *(__nv_bfloat162*)&dst[C + c4]     = L01; *(__nv_bfloat162*)&dst[C + c4 + 2] = L23;
}

// ---------------- fused HMMA projection GEMM (qk + v in one grid) ------------
__global__ __launch_bounds__(256, 2)
void mma_proj(const __nv_bfloat16* __restrict__ A,
              const __nv_bfloat16* __restrict__ wqk, const __nv_bfloat16* __restrict__ wv,
              const float* __restrict__ bqk_, const float* __restrict__ bv_,
              __nv_bfloat16* __restrict__ qkh, __nv_bfloat16* __restrict__ qkl,
              __nv_bfloat16* __restrict__ vvh, __nv_bfloat16* __restrict__ vvl) {
    extern __shared__ __align__(16) __nv_bfloat16 smp[];
    int tid = threadIdx.x, lane = tid & 31, wid = tid >> 5;
    int wm = wid >> 2, wn = wid & 3;
    int row0 = blockIdx.y * 128;
    bool isqk = (blockIdx.x == 4);
    const __nv_bfloat16* Wsp = isqk ? wqk : wv;
    const float* bias = isqk ? bqk_ : bv_;
    __nv_bfloat16* oh = isqk ? qkh : vvh;
    __nv_bfloat16* ol = isqk ? qkl : vvl;
    int Nd  = isqk ? 128 : 512;
    int col0 = isqk ? 0 : blockIdx.x * 128;

    auto tile = [&](int buf, int t) -> __nv_bfloat16* {
        return smp + (buf * 4 + t) * TILE_E;
    };

    float acc[4][4][4];
    #pragma unroll
    for (int mt = 0; mt < 4; mt++)
        #pragma unroll
        for (int nt = 0; nt < 4; nt++)
            #pragma unroll
            for (int i = 0; i < 4; i++) acc[mt][nt][i] = 0.f;

    auto load_chunk = [&](int ch, int buf) {
        int kin = ch * 32;
        #pragma unroll
        for (int j = 0; j < 2; j++) {
            int g = tid + j * 256;
            int m = g >> 2, q = g & 3;
            int gm = row0 + m;
            bool ok = gm < BP;
            const __nv_bfloat16* abase = A + (long)(ok ? gm : 0) * KA + kin + q * 8;
            cp16(smem_u32(tile(buf, 0) + m * 40 + q * 8), abase, ok);
            cp16(smem_u32(tile(buf, 1) + m * 40 + q * 8), abase + C, ok);
            const __nv_bfloat16* bbase = Wsp + (long)(col0 + m) * KA + kin + q * 8;
            cp16(smem_u32(tile(buf, 2) + m * 40 + q * 8), bbase, true);
            cp16(smem_u32(tile(buf, 3) + m * 40 + q * 8), bbase + C, true);
        }
        CP_COMMIT();
    };

    load_chunk(0, 0);
    for (int ch = 0; ch < NCH; ch++) {
        int buf = ch & 1;
        if (ch + 1 < NCH) {
            load_chunk(ch + 1, buf ^ 1);
            CP_WAIT(1);
        } else {
            CP_WAIT(0);
        }
        __syncthreads();
        #pragma unroll
        for (int ks = 0; ks < 2; ks++) {
            int kk = ks * 16;
            uint32_t aH[4][4], aL[4][4], bf[4][2];
            #pragma unroll
            for (int mt = 0; mt < 4; mt++) {
                int arow = wm * 64 + mt * 16 + (lane & 15);
                int acol = kk + ((lane >> 4) << 3);
                uint32_t ad = smem_u32(tile(buf, 0) + arow * 40 + acol);
                asm volatile("ldmatrix.sync.aligned.m8n8.x4.shared.b16 {%0,%1,%2,%3}, [%4];"
                    : "=r"(aH[mt][0]), "=r"(aH[mt][1]), "=r"(aH[mt][2]), "=r"(aH[mt][3]) : "r"(ad));
                uint32_t ad2 = smem_u32(tile(buf, 1) + arow * 40 + acol);
                asm volatile("ldmatrix.sync.aligned.m8n8.x4.shared.b16 {%0,%1,%2,%3}, [%4];"
                    : "=r"(aL[mt][0]), "=r"(aL[mt][1]), "=r"(aL[mt][2]), "=r"(aL[mt][3]) : "r"(ad2));
            }
            #pragma unroll
            for (int np = 0; np < 2; np++) {
                int q = lane >> 3;
                int brow = wn * 32 + np * 16 + ((q >> 1) << 3) + (lane & 7);
                int bcol = kk + ((q & 1) << 3);
                uint32_t bd = smem_u32(tile(buf, 2) + brow * 40 + bcol);
                uint32_t r0, r1, r2, r3;
                asm volatile("ldmatrix.sync.aligned.m8n8.x4.shared.b16 {%0,%1,%2,%3}, [%4];"
                    : "=r"(r0), "=r"(r1), "=r"(r2), "=r"(r3) : "r"(bd));
                bf[np * 2][0] = r0; bf[np * 2][1] = r1;
                bf[np * 2 + 1][0] = r2; bf[np * 2 + 1][1] = r3;
            }
            #pragma unroll
            for (int mt = 0; mt < 4; mt++)
                #pragma unroll
                for (int nt = 0; nt < 4; nt++) {
                    asm volatile("mma.sync.aligned.m16n8k16.row.col.f32.bf16.bf16.f32 "
                        "{%0,%1,%2,%3}, {%4,%5,%6,%7}, {%8,%9}, {%0,%1,%2,%3};"
                        : "+f"(acc[mt][nt][0]), "+f"(acc[mt][nt][1]),
                          "+f"(acc[mt][nt][2]), "+f"(acc[mt][nt][3])
                        : "r"(aH[mt][0]), "r"(aH[mt][1]), "r"(aH[mt][2]), "r"(aH[mt][3]),
                          "r"(bf[nt][0]), "r"(bf[nt][1]));
                    asm volatile("mma.sync.aligned.m16n8k16.row.col.f32.bf16.bf16.f32 "
                        "{%0,%1,%2,%3}, {%4,%5,%6,%7}, {%8,%9}, {%0,%1,%2,%3};"
                        : "+f"(acc[mt][nt][0]), "+f"(acc[mt][nt][1]),
                          "+f"(acc[mt][nt][2]), "+f"(acc[mt][nt][3])
                        : "r"(aL[mt][0]), "r"(aL[mt][1]), "r"(aL[mt][2]), "r"(aL[mt][3]),
                          "r"(bf[nt][0]), "r"(bf[nt][1]));
                }
            #pragma unroll
            for (int np = 0; np < 2; np++) {
                int q = lane >> 3;
                int brow = wn * 32 + np * 16 + ((q >> 1) << 3) + (lane & 7);
                int bcol = kk + ((q & 1) << 3);
                uint32_t bd = smem_u32(tile(buf, 3) + brow * 40 + bcol);
                uint32_t r0, r1, r2, r3;
                asm volatile("ldmatrix.sync.aligned.m8n8.x4.shared.b16 {%0,%1,%2,%3}, [%4];"
                    : "=r"(r0), "=r"(r1), "=r"(r2), "=r"(r3) : "r"(bd));
                bf[np * 2][0] = r0; bf[np * 2][1] = r1;
                bf[np * 2 + 1][0] = r2; bf[np * 2 + 1][1] = r3;
            }
            #pragma unroll
            for (int mt = 0; mt < 4; mt++)
                #pragma unroll
                for (int nt = 0; nt < 4; nt++)
                    asm volatile("mma.sync.aligned.m16n8k16.row.col.f32.bf16.bf16.f32 "
                        "{%0,%1,%2,%3}, {%4,%5,%6,%7}, {%8,%9}, {%0,%1,%2,%3};"
                        : "+f"(acc[mt][nt][0]), "+f"(acc[mt][nt][1]),
                          "+f"(acc[mt][nt][2]), "+f"(acc[mt][nt][3])
                        : "r"(aH[mt][0]), "r"(aH[mt][1]), "r"(aH[mt][2]), "r"(aH[mt][3]),
                          "r"(bf[nt][0]), "r"(bf[nt][1]));
        }
        __syncthreads();
    }

    #pragma unroll
    for (int mt = 0; mt < 4; mt++) {
        #pragma unroll
        for (int nt = 0; nt < 4; nt++) {
            int gn = col0 + wn * 32 + nt * 8 + 2 * (lane & 3);
            float b0 = bias[gn], b1 = bias[gn + 1];
            #pragma unroll
            for (int half = 0; half < 2; half++) {
                int gm = row0 + wm * 64 + mt * 16 + (lane >> 2) + half * 8;
                if (gm >= BP) continue;
                float v0 = acc[mt][nt][half * 2] + b0;
                float v1 = acc[mt][nt][half * 2 + 1] + b1;
                __nv_bfloat16 h0 = __float2bfloat16(v0), h1 = __float2bfloat16(v1);
                __nv_bfloat162 hv; hv.x = h0; hv.y = h1;
                __nv_bfloat162 lv;
                lv.x = __float2bfloat16(v0 - __bfloat162float(h0));
                lv.y = __float2bfloat16(v1 - __bfloat162float(h1));
                *(__nv_bfloat162*)&oh[(long)gm * Nd + gn] = hv;
                *(__nv_bfloat162*)&ol[(long)gm * Nd + gn] = lv;
            }
        }
    }
}

// ---------------- fused HMMA score kernel ------------------------------------
__global__ __launch_bounds__(256, 2)
void score_mma(const __nv_bfloat16* __restrict__ qh, const __nv_bfloat16* __restrict__ ql,
               float* __restrict__ s) {
    extern __shared__ __align__(16) __nv_bfloat16 sms[];
    __nv_bfloat16* Qh = sms;
    __nv_bfloat16* Ql = sms + SC_TE;
    __nv_bfloat16* Kh = sms + 2 * SC_TE;
    __nv_bfloat16* Kl = sms + 3 * SC_TE;
    bool colmode = (blockIdx.x == 0);
    int b = blockIdx.z, yy = blockIdx.y;
    int tid = threadIdx.x, lane = tid & 31, wid = tid >> 5;
    int wm = wid >> 2, wn = wid & 3;
    const int rstr = colmode ? W : 1;
    long line0 = (long)b * P + (colmode ? yy : (long)yy * W);

    for (int idx = tid; idx < 1024; idx += 256) {
        int r = idx >> 3, g8 = (idx & 7) * 8;
        bool ok = r < 97;
        long base = (line0 + (long)r * rstr) * 128;
        uint4 z = make_uint4(0u, 0u, 0u, 0u);
        uint4 v0 = ok ? *(const uint4*)&qh[base + g8]      : z;
        uint4 v1 = ok ? *(const uint4*)&ql[base + g8]      : z;
        uint4 v2 = ok ? *(const uint4*)&qh[base + 64 + g8] : z;
        uint4 v3 = ok ? *(const uint4*)&ql[base + 64 + g8] : z;
        *(uint4*)&Qh[r * 72 + g8] = v0;
        *(uint4*)&Ql[r * 72 + g8] = v1;
        *(uint4*)&Kh[r * 72 + g8] = v2;
        *(uint4*)&Kl[r * 72 + g8] = v3;
    }
    __syncthreads();

    float acc[4][4][4];
    #pragma unroll
    for (int mt = 0; mt < 4; mt++)
        #pragma unroll
        for (int nt = 0; nt < 4; nt++)
            #pragma unroll
            for (int i = 0; i < 4; i++) acc[mt][nt][i] = 0.f;

    #pragma unroll
    for (int ck = 0; ck < 4; ck++) {
        int kk = ck * 16;
        uint32_t aH[4][4], aL[4][4], bH[4][2], bL[4][2];
        #pragma unroll
        for (int mt = 0; mt < 4; mt++) {
            int arow = wm * 64 + mt * 16 + (lane & 15);
            int acol = kk + ((lane >> 4) << 3);
            uint32_t ad = smem_u32(Qh + arow * 72 + acol);
            asm volatile("ldmatrix.sync.aligned.m8n8.x4.shared.b16 {%0,%1,%2,%3}, [%4];"
                : "=r"(aH[mt][0]), "=r"(aH[mt][1]), "=r"(aH[mt][2]), "=r"(aH[mt][3]) : "r"(ad));
            uint32_t ad2 = smem_u32(Ql + arow * 72 + acol);
            asm volatile("ldmatrix.sync.aligned.m8n8.x4.shared.b16 {%0,%1,%2,%3}, [%4];"
                : "=r"(aL[mt][0]), "=r"(aL[mt][1]), "=r"(aL[mt][2]), "=r"(aL[mt][3]) : "r"(ad2));
        }
        #pragma unroll
        for (int np = 0; np < 2; np++) {
            int q = lane >> 3;
            int brow = wn * 32 + np * 16 + ((q >> 1) << 3) + (lane & 7);
            int bcol = kk + ((q & 1) << 3);
            uint32_t r0, r1, r2, r3;
            uint32_t bd = smem_u32(Kh + brow * 72 + bcol);
            asm volatile("ldmatrix.sync.aligned.m8n8.x4.shared.b16 {%0,%1,%2,%3}, [%4];"
                : "=r"(r0), "=r"(r1), "=r"(r2), "=r"(r3) : "r"(bd));
            bH[np * 2][0] = r0; bH[np * 2][1] = r1;
            bH[np * 2 + 1][0] = r2; bH[np * 2 + 1][1] = r3;
            uint32_t bd2 = smem_u32(Kl + brow * 72 + bcol);
            asm volatile("ldmatrix.sync.aligned.m8n8.x4.shared.b16 {%0,%1,%2,%3}, [%4];"
                : "=r"(r0), "=r"(r1), "=r"(r2), "=r"(r3) : "r"(bd2));
            bL[np * 2][0] = r0; bL[np * 2][1] = r1;
            bL[np * 2 + 1][0] = r2; bL[np * 2 + 1][1] = r3;
        }
        #pragma unroll
        for (int mt = 0; mt < 4; mt++)
            #pragma unroll
            for (int nt = 0; nt < 4; nt++) {
                asm volatile("mma.sync.aligned.m16n8k16.row.col.f32.bf16.bf16.f32 "
                    "{%0,%1,%2,%3}, {%4,%5,%6,%7}, {%8,%9}, {%0,%1,%2,%3};"
                    : "+f"(acc[mt][nt][0]), "+f"(acc[mt][nt][1]),
                      "+f"(acc[mt][nt][2]), "+f"(acc[mt][nt][3])
                    : "r"(aH[mt][0]), "r"(aH[mt][1]), "r"(aH[mt][2]), "r"(aH[mt][3]),
                      "r"(bH[nt][0]), "r"(bH[nt][1]));
                asm volatile("mma.sync.aligned.m16n8k16.row.col.f32.bf16.bf16.f32 "
                    "{%0,%1,%2,%3}, {%4,%5,%6,%7}, {%8,%9}, {%0,%1,%2,%3};"
                    : "+f"(acc[mt][nt][0]), "+f"(acc[mt][nt][1]),
                      "+f"(acc[mt][nt][2]), "+f"(acc[mt][nt][3])
                    : "r"(aL[mt][0]), "r"(aL[mt][1]), "r"(aL[mt][2]), "r"(aL[mt][3]),
                      "r"(bH[nt][0]), "r"(bH[nt][1]));
                asm volatile("mma.sync.aligned.m16n8k16.row.col.f32.bf16.bf16.f32 "
                    "{%0,%1,%2,%3}, {%4,%5,%6,%7}, {%8,%9}, {%0,%1,%2,%3};"
                    : "+f"(acc[mt][nt][0]), "+f"(acc[mt][nt][1]),
                      "+f"(acc[mt][nt][2]), "+f"(acc[mt][nt][3])
                    : "r"(aH[mt][0]), "r"(aH[mt][1]), "r"(aH[mt][2]), "r"(aH[mt][3]),
                      "r"(bL[nt][0]), "r"(bL[nt][1]));
            }
    }

    #pragma unroll
    for (int mt = 0; mt < 4; mt++) {
        #pragma unroll
        for (int nt = 0; nt < 4; nt++) {
            int gn = wn * 32 + nt * 8 + 2 * (lane & 3);
            #pragma unroll
            for (int half = 0; half < 2; half++) {
                int r = wm * 64 + mt * 16 + (lane >> 2) + half * 8;
                if (r >= 97) continue;
                float* outp = s + (line0 + (long)r * rstr) * S + (colmode ? 0 : 97);
                float v0 = acc[mt][nt][half * 2];
                float v1 = acc[mt][nt][half * 2 + 1];
                if (colmode && r == gn)     v0 += NEG_INF;
                if (colmode && r == gn + 1) v1 += NEG_INF;
                if (gn < 97)     outp[gn]     = v0;
                if (gn + 1 < 97) outp[gn + 1] = v1;
            }
        }
    }
}

// ---------------- softmax ----------------------------------------------------
__global__ __launch_bounds__(256)
void softmax194(const float* __restrict__ s, __nv_bfloat16* __restrict__ sh,
                __nv_bfloat16* __restrict__ sl) {
    long row = (long)blockIdx.x * 8 + (threadIdx.x >> 5);
    int lane = threadIdx.x & 31;
    const float* r = s + row * S;
    float v[7];
    float m = -3.0e38f;
    #pragma unroll
    for (int t = 0; t < 7; t++) {
        int idx = lane + 32 * t;
        v[t] = (idx < S) ? r[idx] : -3.0e38f;
        m = fmaxf(m, v[t]);
    }
    #pragma unroll
    for (int o = 16; o > 0; o >>= 1) m = fmaxf(m, __shfl_xor_sync(0xffffffffu, m, o));
    float sum = 0.f;
    #pragma unroll
    for (int t = 0; t < 7; t++) { v[t] = __expf(v[t] - m); sum += v[t]; }
    #pragma unroll
    for (int o = 16; o > 0; o >>= 1) sum += __shfl_xor_sync(0xffffffffu, sum, o);
    float inv = 1.0f / sum;
    __nv_bfloat16* shr = sh + row * SP;
    __nv_bfloat16* slr = sl + row * SP;
    #pragma unroll
    for (int t = 0; t < 7; t++) {
        int idx = lane + 32 * t;
        if (idx < S) {
            float val = v[t] * inv;
            int o = idx < 97 ? idx : OFFW + (idx - 97);
            __nv_bfloat16 hi = __float2bfloat16(val);
            shr[o] = hi;
            slr[o] = __float2bfloat16(val - __bfloat162float(hi));
        }
    }
}

// ---------------- HMMA apply (round-12 shape, residual from xs) --------------
template<bool COLMODE>
__global__ __launch_bounds__(256, 2)
void apply_mma(const __nv_bfloat16* __restrict__ sh, const __nv_bfloat16* __restrict__ sl,
               const __nv_bfloat16* __restrict__ vh, const __nv_bfloat16* __restrict__ vl,
               float* __restrict__ y, const __nv_bfloat16* __restrict__ xsr,
               const float* __restrict__ gamma, __nv_bfloat16* __restrict__ xsw) {
    extern __shared__ __align__(16) __nv_bfloat16 sma[];
    __nv_bfloat16* Ah = sma;                 // [2][128][40]
    __nv_bfloat16* Al = sma + 2 * APT;
    __nv_bfloat16* Vh = sma + 4 * APT;       // [2][32][136]
    __nv_bfloat16* Vl = sma + 4 * APT + 2 * VPT;
    int b = blockIdx.z, yy = blockIdx.y, c0 = blockIdx.x * 128;
    int tid = threadIdx.x, lane = tid & 31, wid = tid >> 5;
    int wm = wid >> 2, wn = wid & 3;
    const int rstr = COLMODE ? W : 1;
    long line0 = (long)b * P + (COLMODE ? yy : (long)yy * W);
    const int off = COLMODE ? 0 : OFFW;

    float acc[4][4][4];
    #pragma unroll
    for (int mt = 0; mt < 4; mt++)
        #pragma unroll
        for (int nt = 0; nt < 4; nt++)
            #pragma unroll
            for (int i = 0; i < 4; i++) acc[mt][nt][i] = 0.f;

    auto load_chunk = [&](int ch, int buf) {
        int g0 = ch * 32;
        #pragma unroll
        for (int j = 0; j < 2; j++) {
            int idx = tid + j * 256;
            int r = idx >> 2, q = idx & 3;
            int gg = g0 + q * 8;
            int ab = (r < 97 && gg < 97) ? min(97 - gg, 8) * 2 : 0;
            long rowoff = (line0 + (long)(r < 97 ? r : 0) * rstr) * SP + off + (gg < 97 ? gg : 0);
            cp16v(smem_u32(Ah + buf * APT + r * 40 + q * 8), sh + rowoff, ab);
            cp16v(smem_u32(Al + buf * APT + r * 40 + q * 8), sl + rowoff, ab);
        }
        #pragma unroll
        for (int j = 0; j < 2; j++) {
            int idx = tid + j * 256;
            int g = idx >> 4, c8 = (idx & 15) * 8;
            int gabs = g0 + g;
            int vb = (gabs < 97) ? 16 : 0;
            long nk = (line0 + (long)(gabs < 97 ? gabs : 0) * rstr) * C + c0 + c8;
            cp16v(smem_u32(Vh + buf * VPT + g * 136 + c8), vh + nk, vb);
            cp16v(smem_u32(Vl + buf * VPT + g * 136 + c8), vl + nk, vb);
        }
        CP_COMMIT();
    };

    load_chunk(0, 0);
    for (int ch = 0; ch < 4; ch++) {
        int cur = ch & 1;
        if (ch + 1 < 4) {
            load_chunk(ch + 1, cur ^ 1);
            CP_WAIT(1);
        } else {
            CP_WAIT(0);
        }
        __syncthreads();
        #pragma unroll
        for (int ks = 0; ks < 2; ks++) {
            int kk = ks * 16;
            uint32_t aH[4][4], aL[4][4], bf[4][2];
            #pragma unroll
            for (int mt = 0; mt < 4; mt++) {
                int arow = wm * 64 + mt * 16 + (lane & 15);
                int acol = kk + ((lane >> 4) << 3);
                uint32_t ad = smem_u32(Ah + cur * APT + arow * 40 + acol);
                asm volatile("ldmatrix.sync.aligned.m8n8.x4.shared.b16 {%0,%1,%2,%3}, [%4];"
                    : "=r"(aH[mt][0]), "=r"(aH[mt][1]), "=r"(aH[mt][2]), "=r"(aH[mt][3]) : "r"(ad));
                uint32_t ad2 = smem_u32(Al + cur * APT + arow * 40 + acol);
                asm volatile("ldmatrix.sync.aligned.m8n8.x4.shared.b16 {%0,%1,%2,%3}, [%4];"
                    : "=r"(aL[mt][0]), "=r"(aL[mt][1]), "=r"(aL[mt][2]), "=r"(aL[mt][3]) : "r"(ad2));
            }
            #pragma unroll
            for (int np = 0; np < 2; np++) {
                int q = lane >> 3;
                int krow = kk + ((q & 1) << 3) + (lane & 7);
                int ncol = wn * 32 + np * 16 + ((q >> 1) << 3);
                uint32_t r0, r1, r2, r3;
                uint32_t bd = smem_u32(Vh + cur * VPT + krow * 136 + ncol);
                asm volatile("ldmatrix.sync.aligned.m8n8.x4.trans.shared.b16 {%0,%1,%2,%3}, [%4];"
                    : "=r"(r0), "=r"(r1), "=r"(r2), "=r"(r3) : "r"(bd));
                bf[np * 2][0] = r0; bf[np * 2][1] = r1;
                bf[np * 2 + 1][0] = r2; bf[np * 2 + 1][1] = r3;
            }
            #pragma unroll
            for (int mt = 0; mt < 4; mt++)
                #pragma unroll
                for (int nt = 0; nt < 4; nt++) {
                    asm volatile("mma.sync.aligned.m16n8k16.row.col.f32.bf16.bf16.f32 "
                        "{%0,%1,%2,%3}, {%4,%5,%6,%7}, {%8,%9}, {%0,%1,%2,%3};"
                        : "+f"(acc[mt][nt][0]), "+f"(acc[mt][nt][1]),
                          "+f"(acc[mt][nt][2]), "+f"(acc[mt][nt][3])
                        : "r"(aH[mt][0]), "r"(aH[mt][1]), "r"(aH[mt][2]), "r"(aH[mt][3]),
                          "r"(bf[nt][0]), "r"(bf[nt][1]));
                    asm volatile("mma.sync.aligned.m16n8k16.row.col.f32.bf16.bf16.f32 "
                        "{%0,%1,%2,%3}, {%4,%5,%6,%7}, {%8,%9}, {%0,%1,%2,%3};"
                        : "+f"(acc[mt][nt][0]), "+f"(acc[mt][nt][1]),
                          "+f"(acc[mt][nt][2]), "+f"(acc[mt][nt][3])
                        : "r"(aL[mt][0]), "r"(aL[mt][1]), "r"(aL[mt][2]), "r"(aL[mt][3]),
                          "r"(bf[nt][0]), "r"(bf[nt][1]));
                }
            #pragma unroll
            for (int np = 0; np < 2; np++) {
                int q = lane >> 3;
                int krow = kk + ((q & 1) << 3) + (lane & 7);
                int ncol = wn * 32 + np * 16 + ((q >> 1) << 3);
                uint32_t r0, r1, r2, r3;
                uint32_t bd = smem_u32(Vl + cur * VPT + krow * 136 + ncol);
                asm volatile("ldmatrix.sync.aligned.m8n8.x4.trans.shared.b16 {%0,%1,%2,%3}, [%4];"
                    : "=r"(r0), "=r"(r1), "=r"(r2), "=r"(r3) : "r"(bd));
                bf[np * 2][0] = r0; bf[np * 2][1] = r1;
                bf[np * 2 + 1][0] = r2; bf[np * 2 + 1][1] = r3;
            }
            #pragma unroll
            for (int mt = 0; mt < 4; mt++)
                #pragma unroll
                for (int nt = 0; nt < 4; nt++)
                    asm volatile("mma.sync.aligned.m16n8k16.row.col.f32.bf16.bf16.f32 "
                        "{%0,%1,%2,%3}, {%4,%5,%6,%7}, {%8,%9}, {%0,%1,%2,%3};"
                        : "+f"(acc[mt][nt][0]), "+f"(acc[mt][nt][1]),
                          "+f"(acc[mt][nt][2]), "+f"(acc[mt][nt][3])
                        : "r"(aH[mt][0]), "r"(aH[mt][1]), "r"(aH[mt][2]), "r"(aH[mt][3]),
                          "r"(bf[nt][0]), "r"(bf[nt][1]));
        }
        __syncthreads();
    }

    float gmv = COLMODE ? 0.f : __ldg(gamma);
    #pragma unroll
    for (int mt = 0; mt < 4; mt++) {
        #pragma unroll
        for (int nt = 0; nt < 4; nt++) {
            int gn = c0 + wn * 32 + nt * 8 + 2 * (lane & 3);
            #pragma unroll
            for (int half = 0; half < 2; half++) {
                int r = wm * 64 + mt * 16 + (lane >> 2) + half * 8;
                if (r >= 97) continue;
                long node = line0 + (long)r * rstr;
                long addr = node * C + gn;
                float a0 = acc[mt][nt][half * 2], a1 = acc[mt][nt][half * 2 + 1];
                if (COLMODE) {
                    float2 o; o.x = a0; o.y = a1;
                    *(float2*)&y[addr] = o;
                } else {
                    float2 p = *(const float2*)&y[addr];
                    // residual x from split storage (hi + lo)
                    __nv_bfloat162 rh = *(const __nv_bfloat162*)&xsr[node * KA + gn];
                    __nv_bfloat162 rl = *(const __nv_bfloat162*)&xsr[node * KA + C + gn];
                    float xx0 = __bfloat162float(rh.x) + __bfloat162float(rl.x);
                    float xx1 = __bfloat162float(rh.y) + __bfloat162float(rl.y);
                    float2 o;
                    o.x = gmv * (p.x + a0) + xx0;
                    o.y = gmv * (p.y + a1) + xx1;
                    *(float2*)&y[addr] = o;
                    if (xsw) {
                        __nv_bfloat16 h0 = __float2bfloat16(o.x), h1 = __float2bfloat16(o.y);
                        __nv_bfloat162 hv; hv.x = h0; hv.y = h1;
                        __nv_bfloat162 lv;
                        lv.x = __float2bfloat16(o.x - __bfloat162float(h0));
                        lv.y = __float2bfloat16(o.y - __bfloat162float(h1));
                        *(__nv_bfloat162*)&xsw[node * KA + gn]     = hv;
                        *(__nv_bfloat162*)&xsw[node * KA + C + gn] = lv;
                    }
                }
            }
        }
    }
}

// ---------------- launch -----------------------------------------------------
extern "C" void kernel_launch(void* const* d_in, const int* in_sizes, int n_in,
                              void* d_out, int out_size) {
    const float* x     = (const float*)d_in[0];
    const float* Wq    = (const float*)d_in[1];
    const float* bq    = (const float*)d_in[2];
    const float* Wk    = (const float*)d_in[3];
    const float* bk    = (const float*)d_in[4];
    const float* Wv    = (const float*)d_in[5];
    const float* bv    = (const float*)d_in[6];
    const float* gamma = (const float*)d_in[7];
    float* out = (float*)d_out;

    float *xT, *yT, *sp, *bqk;
    __nv_bfloat16 *xs, *wsv, *wsqk, *sh, *sl, *vh, *vl, *qkh, *qkl;
    cudaGetSymbolAddress((void**)&xT,  g_xT);
    cudaGetSymbolAddress((void**)&yT,  g_yT);
    cudaGetSymbolAddress((void**)&sp,  g_s);
    cudaGetSymbolAddress((void**)&xs,   g_xs);
    cudaGetSymbolAddress((void**)&wsv,  g_wsv);
    cudaGetSymbolAddress((void**)&wsqk, g_wsqk);
    cudaGetSymbolAddress((void**)&bqk,  g_bqk);
    cudaGetSymbolAddress((void**)&sh,  g_sh);
    cudaGetSymbolAddress((void**)&sl,  g_sl);
    cudaGetSymbolAddress((void**)&vh,  g_vh);
    cudaGetSymbolAddress((void**)&vl,  g_vl);
    cudaGetSymbolAddress((void**)&qkh, g_qkh);
    cudaGetSymbolAddress((void**)&qkl, g_qkl);

    cudaFuncSetAttribute(mma_proj,  cudaFuncAttributeMaxDynamicSharedMemorySize, SMEM_PROJ);
    cudaFuncSetAttribute(score_mma, cudaFuncAttributeMaxDynamicSharedMemorySize, SMEM_SCORE);
    cudaFuncSetAttribute(apply_mma<true >, cudaFuncAttributeMaxDynamicSharedMemorySize, SMEM_APPLY);
    cudaFuncSetAttribute(apply_mma<false>, cudaFuncAttributeMaxDynamicSharedMemorySize, SMEM_APPLY);

    dim3 tgrid((P + 31) / 32, C / 32, B), tthr(32, 8);
    transpose_in<<<tgrid, tthr>>>(x, xs);
    prep_w<<<320, 256>>>(Wq, Wk, Wv, bq, bk);

    for (int it = 0; it < 2; it++) {
        float* Y = it ? xT : yT;
        mma_proj<<<dim3(5, MBLK), 256, SMEM_PROJ>>>(xs, wsqk, wsv, bqk, bv, qkh, qkl, vh, vl);
        score_mma<<<dim3(2, W, B), 256, SMEM_SCORE>>>(qkh, qkl, sp);
        softmax194<<<P, 256>>>(sp, sh, sl);
        apply_mma<true ><<<dim3(4, W, B), 256, SMEM_APPLY>>>(sh, sl, vh, vl, Y, xs, gamma, nullptr);
        apply_mma<false><<<dim3(4, H, B), 256, SMEM_APPLY>>>(sh, sl, vh, vl, Y, xs, gamma, it == 0 ? xs : nullptr);
    }

    transpose_out<<<tgrid, tthr>>>(xT, out);
}

// round 15
// speedup vs baseline: 1.0953x; 1.0953x over previous
#include <cuda_runtime.h>
#include <cuda_bf16.h>
#include <cstdint>

namespace {
constexpr int B   = 8;
constexpr int H   = 97;
constexpr int W   = 97;
constexpr int C   = 512;
constexpr int P   = H * W;        // 9409
constexpr int S   = H + W;        // 194
constexpr int BP  = B * P;        // 75272
constexpr int KA  = 2 * C;        // 1024: [hi | lo] storage
constexpr int NCH = 16;           // proj: 16 physical chunks of k32
constexpr int MBLK = (BP + 127) / 128;   // 589
constexpr int SP   = 224;         // padded attention row stride (bf16)
constexpr int OFFW = 112;         // aW section offset within SP
constexpr int TILE_E = 128 * 40;  // proj smem tile elems
constexpr int SMEM_PROJ = 8 * TILE_E * 2;     // 81920 bytes
constexpr int SC_TE = 128 * 72;               // score tile elems
constexpr int SMEM_SCORE = 4 * SC_TE * 2;     // 73728 bytes
// apply: A tiles 128x40, V tiles 32x136, 2 stages, hi+lo
constexpr int APT = 128 * 40;
constexpr int VPT = 32 * 136;
constexpr int SMEM_APPLY = (4 * APT + 4 * VPT) * 2;   // 75776 bytes
constexpr float NEG_INF = -1000000000.0f;
}

// ---------------- scratch ---------------------------------------------------
__device__ float g_xT[BP * C];
__device__ float g_yT[BP * C];
__device__ float g_s [BP * S];
__device__ __nv_bfloat16 g_qkh[(long)BP * 128];
__device__ __nv_bfloat16 g_qkl[(long)BP * 128];
__device__ __nv_bfloat16 g_sh[(long)BP * SP];
__device__ __nv_bfloat16 g_sl[(long)BP * SP];
__device__ __nv_bfloat16 g_vh[(long)BP * C];
__device__ __nv_bfloat16 g_vl[(long)BP * C];
__device__ __nv_bfloat16 g_xs[(long)BP * KA];     // split x: [hi | lo]
__device__ __nv_bfloat16 g_wsv [C * KA];
__device__ __nv_bfloat16 g_wsqk[128 * KA];
__device__ float g_bqk[128];

__device__ __forceinline__ uint32_t smem_u32(const void* p) {
    uint32_t a;
    asm("{ .reg .u64 t; cvta.to.shared.u64 t, %1; cvt.u32.u64 %0, t; }" : "=r"(a) : "l"(p));
    return a;
}
__device__ __forceinline__ void cp16(uint32_t dst, const void* src, bool valid) {
    int sz = valid ? 16 : 0;
    asm volatile("cp.async.cg.shared.global [%0], [%1], 16, %2;" :: "r"(dst), "l"(src), "r"(sz));
}
__device__ __forceinline__ void cp16v(uint32_t dst, const void* src, int bytes) {
    asm volatile("cp.async.cg.shared.global [%0], [%1], 16, %2;" :: "r"(dst), "l"(src), "r"(bytes));
}
#define CP_COMMIT() asm volatile("cp.async.commit_group;" ::: "memory")
#define CP_WAIT(n)  asm volatile("cp.async.wait_group %0;" :: "n"(n) : "memory")

// ---------------- transpose in: (B,C,P) -> (B,P,C) f32 + split bf16 ----------
__global__ void transpose_in(const float* __restrict__ src, float* __restrict__ dst,
                             __nv_bfloat16* __restrict__ xs) {
    __shared__ float t[32][33];
    int b = blockIdx.z, n0 = blockIdx.x * 32, c0 = blockIdx.y * 32;
    const float* sp = src + (long)b * C * P;
    for (int i = threadIdx.y; i < 32; i += 8) {
        int n = n0 + threadIdx.x;
        if (n < P) t[i][threadIdx.x] = sp[(long)(c0 + i) * P + n];
    }
    __syncthreads();
    for (int i = threadIdx.y; i < 32; i += 8) {
        int n = n0 + i;
        if (n < P) {
            float v = t[threadIdx.x][i];
            long m = (long)b * P + n;
            dst[m * C + c0 + threadIdx.x] = v;
            __nv_bfloat16 hv = __float2bfloat16(v);
            xs[m * KA + c0 + threadIdx.x]     = hv;
            xs[m * KA + C + c0 + threadIdx.x] = __float2bfloat16(v - __bfloat162float(hv));
        }
    }
}
__global__ void transpose_out(const float* __restrict__ src, float* __restrict__ dst) {
    __shared__ float t[32][33];
    int b = blockIdx.z, n0 = blockIdx.x * 32, c0 = blockIdx.y * 32;
    const float* sp = src + (long)b * P * C;
    float*       dp = dst + (long)b * C * P;
    for (int i = threadIdx.y; i < 32; i += 8) {
        int n = n0 + i;
        if (n < P) t[i][threadIdx.x] = sp[(long)n * C + c0 + threadIdx.x];
    }
    __syncthreads();
    for (int i = threadIdx.y; i < 32; i += 8) {
        int n = n0 + threadIdx.x;
        if (n < P) dp[(long)(c0 + i) * P + n] = t[threadIdx.x][i];
    }
}

__global__ __launch_bounds__(256) void prep_w(const float* __restrict__ Wq, const float* __restrict__ Wk,
                                              const float* __restrict__ Wv, const float* __restrict__ bq,
                                              const float* __restrict__ bk) {
    int i = blockIdx.x * 256 + threadIdx.x;
    if (blockIdx.x == 0 && threadIdx.x < 128)
        g_bqk[threadIdx.x] = threadIdx.x < 64 ? bq[threadIdx.x] : bk[threadIdx.x - 64];
    if (i >= 640 * 128) return;
    int r = i >> 7, c4 = (i & 127) * 4;
    const float* src; __nv_bfloat16* dst;
    if (r < 512) { src = Wv + (long)r * C + c4; dst = g_wsv + (long)r * KA; }
    else {
        int rr = r - 512;
        src = (rr < 64 ? Wq + (long)rr * C : Wk + (long)(rr - 64) * C) + c4;
        dst = g_wsqk + (long)rr * KA;
    }
    float4 x = *(const float4*)src;
    __nv_bfloat16 h0 = __float2bfloat16(x.x), h1 = __float2bfloat16(x.y);
    __nv_bfloat16 h2 = __float2bfloat16(x.z), h3 = __float2bfloat16(x.w);
    __nv_bfloat16 l0 = __float2bfloat16(x.x - __bfloat162float(h0));
    __nv_bfloat16 l1 = __float2bfloat16(x.y - __bfloat162float(h1));
    __nv_bfloat16 l2 = __float2bfloat16(x.z - __bfloat162float(h2));
    __nv_bfloat16 l3 = __float2bfloat16(x.w - __bfloat162float(h3));
    __nv_bfloat162 H01; H01.x = h0; H01.y = h1;
    __nv_bfloat162 H23; H23.x = h2; H23.y = h3;
    __nv_bfloat162 L01; L01.x = l0; L01.y = l1;
    __nv_bfloat162 L23; L23.x = l2; L23.y = l3;
    *(__nv_bfloat162*)&dst[c4]         = H01; *(__nv_bfloat162*)&dst[c4 + 2]     = H23;
    *(__nv_bfloat162*)&dst[C + c4]     = L01; *(__nv_bfloat162*)&dst[C + c4 + 2] = L23;
}

// ---------------- fused HMMA projection GEMM (qk + v in one grid) ------------
__global__ __launch_bounds__(256, 2)
void mma_proj(const __nv_bfloat16* __restrict__ A,
              const __nv_bfloat16* __restrict__ wqk, const __nv_bfloat16* __restrict__ wv,
              const float* __restrict__ bqk_, const float* __restrict__ bv_,
              __nv_bfloat16* __restrict__ qkh, __nv_bfloat16* __restrict__ qkl,
              __nv_bfloat16* __restrict__ vvh, __nv_bfloat16* __restrict__ vvl) {
    extern __shared__ __align__(16) __nv_bfloat16 smp[];
    int tid = threadIdx.x, lane = tid & 31, wid = tid >> 5;
    int wm = wid >> 2, wn = wid & 3;
    int row0 = blockIdx.y * 128;
    bool isqk = (blockIdx.x == 4);
    const __nv_bfloat16* Wsp = isqk ? wqk : wv;
    const float* bias = isqk ? bqk_ : bv_;
    __nv_bfloat16* oh = isqk ? qkh : vvh;
    __nv_bfloat16* ol = isqk ? qkl : vvl;
    int Nd  = isqk ? 128 : 512;
    int col0 = isqk ? 0 : blockIdx.x * 128;

    auto tile = [&](int buf, int t) -> __nv_bfloat16* {
        return smp + (buf * 4 + t) * TILE_E;
    };

    float acc[4][4][4];
    #pragma unroll
    for (int mt = 0; mt < 4; mt++)
        #pragma unroll
        for (int nt = 0; nt < 4; nt++)
            #pragma unroll
            for (int i = 0; i < 4; i++) acc[mt][nt][i] = 0.f;

    auto load_chunk = [&](int ch, int buf) {
        int kin = ch * 32;
        #pragma unroll
        for (int j = 0; j < 2; j++) {
            int g = tid + j * 256;
            int m = g >> 2, q = g & 3;
            int gm = row0 + m;
            bool ok = gm < BP;
            const __nv_bfloat16* abase = A + (long)(ok ? gm : 0) * KA + kin + q * 8;
            cp16(smem_u32(tile(buf, 0) + m * 40 + q * 8), abase, ok);
            cp16(smem_u32(tile(buf, 1) + m * 40 + q * 8), abase + C, ok);
            const __nv_bfloat16* bbase = Wsp + (long)(col0 + m) * KA + kin + q * 8;
            cp16(smem_u32(tile(buf, 2) + m * 40 + q * 8), bbase, true);
            cp16(smem_u32(tile(buf, 3) + m * 40 + q * 8), bbase + C, true);
        }
        CP_COMMIT();
    };

    load_chunk(0, 0);
    for (int ch = 0; ch < NCH; ch++) {
        int buf = ch & 1;
        if (ch + 1 < NCH) {
            load_chunk(ch + 1, buf ^ 1);
            CP_WAIT(1);
        } else {
            CP_WAIT(0);
        }
        __syncthreads();
        #pragma unroll
        for (int ks = 0; ks < 2; ks++) {
            int kk = ks * 16;
            uint32_t aH[4][4], aL[4][4], bf[4][2];
            #pragma unroll
            for (int mt = 0; mt < 4; mt++) {
                int arow = wm * 64 + mt * 16 + (lane & 15);
                int acol = kk + ((lane >> 4) << 3);
                uint32_t ad = smem_u32(tile(buf, 0) + arow * 40 + acol);
                asm volatile("ldmatrix.sync.aligned.m8n8.x4.shared.b16 {%0,%1,%2,%3}, [%4];"
                    : "=r"(aH[mt][0]), "=r"(aH[mt][1]), "=r"(aH[mt][2]), "=r"(aH[mt][3]) : "r"(ad));
                uint32_t ad2 = smem_u32(tile(buf, 1) + arow * 40 + acol);
                asm volatile("ldmatrix.sync.aligned.m8n8.x4.shared.b16 {%0,%1,%2,%3}, [%4];"
                    : "=r"(aL[mt][0]), "=r"(aL[mt][1]), "=r"(aL[mt][2]), "=r"(aL[mt][3]) : "r"(ad2));
            }
            #pragma unroll
            for (int np = 0; np < 2; np++) {
                int q = lane >> 3;
                int brow = wn * 32 + np * 16 + ((q >> 1) << 3) + (lane & 7);
                int bcol = kk + ((q & 1) << 3);
                uint32_t bd = smem_u32(tile(buf, 2) + brow * 40 + bcol);
                uint32_t r0, r1, r2, r3;
                asm volatile("ldmatrix.sync.aligned.m8n8.x4.shared.b16 {%0,%1,%2,%3}, [%4];"
                    : "=r"(r0), "=r"(r1), "=r"(r2), "=r"(r3) : "r"(bd));
                bf[np * 2][0] = r0; bf[np * 2][1] = r1;
                bf[np * 2 + 1][0] = r2; bf[np * 2 + 1][1] = r3;
            }
            #pragma unroll
            for (int mt = 0; mt < 4; mt++)
                #pragma unroll
                for (int nt = 0; nt < 4; nt++) {
                    asm volatile("mma.sync.aligned.m16n8k16.row.col.f32.bf16.bf16.f32 "
                        "{%0,%1,%2,%3}, {%4,%5,%6,%7}, {%8,%9}, {%0,%1,%2,%3};"
                        : "+f"(acc[mt][nt][0]), "+f"(acc[mt][nt][1]),
                          "+f"(acc[mt][nt][2]), "+f"(acc[mt][nt][3])
                        : "r"(aH[mt][0]), "r"(aH[mt][1]), "r"(aH[mt][2]), "r"(aH[mt][3]),
                          "r"(bf[nt][0]), "r"(bf[nt][1]));
                    asm volatile("mma.sync.aligned.m16n8k16.row.col.f32.bf16.bf16.f32 "
                        "{%0,%1,%2,%3}, {%4,%5,%6,%7}, {%8,%9}, {%0,%1,%2,%3};"
                        : "+f"(acc[mt][nt][0]), "+f"(acc[mt][nt][1]),
                          "+f"(acc[mt][nt][2]), "+f"(acc[mt][nt][3])
                        : "r"(aL[mt][0]), "r"(aL[mt][1]), "r"(aL[mt][2]), "r"(aL[mt][3]),
                          "r"(bf[nt][0]), "r"(bf[nt][1]));
                }
            #pragma unroll
            for (int np = 0; np < 2; np++) {
                int q = lane >> 3;
                int brow = wn * 32 + np * 16 + ((q >> 1) << 3) + (lane & 7);
                int bcol = kk + ((q & 1) << 3);
                uint32_t bd = smem_u32(tile(buf, 3) + brow * 40 + bcol);
                uint32_t r0, r1, r2, r3;
                asm volatile("ldmatrix.sync.aligned.m8n8.x4.shared.b16 {%0,%1,%2,%3}, [%4];"
                    : "=r"(r0), "=r"(r1), "=r"(r2), "=r"(r3) : "r"(bd));
                bf[np * 2][0] = r0; bf[np * 2][1] = r1;
                bf[np * 2 + 1][0] = r2; bf[np * 2 + 1][1] = r3;
            }
            #pragma unroll
            for (int mt = 0; mt < 4; mt++)
                #pragma unroll
                for (int nt = 0; nt < 4; nt++)
                    asm volatile("mma.sync.aligned.m16n8k16.row.col.f32.bf16.bf16.f32 "
                        "{%0,%1,%2,%3}, {%4,%5,%6,%7}, {%8,%9}, {%0,%1,%2,%3};"
                        : "+f"(acc[mt][nt][0]), "+f"(acc[mt][nt][1]),
                          "+f"(acc[mt][nt][2]), "+f"(acc[mt][nt][3])
                        : "r"(aH[mt][0]), "r"(aH[mt][1]), "r"(aH[mt][2]), "r"(aH[mt][3]),
                          "r"(bf[nt][0]), "r"(bf[nt][1]));
        }
        __syncthreads();
    }

    #pragma unroll
    for (int mt = 0; mt < 4; mt++) {
        #pragma unroll
        for (int nt = 0; nt < 4; nt++) {
            int gn = col0 + wn * 32 + nt * 8 + 2 * (lane & 3);
            float b0 = bias[gn], b1 = bias[gn + 1];
            #pragma unroll
            for (int half = 0; half < 2; half++) {
                int gm = row0 + wm * 64 + mt * 16 + (lane >> 2) + half * 8;
                if (gm >= BP) continue;
                float v0 = acc[mt][nt][half * 2] + b0;
                float v1 = acc[mt][nt][half * 2 + 1] + b1;
                __nv_bfloat16 h0 = __float2bfloat16(v0), h1 = __float2bfloat16(v1);
                __nv_bfloat162 hv; hv.x = h0; hv.y = h1;
                __nv_bfloat162 lv;
                lv.x = __float2bfloat16(v0 - __bfloat162float(h0));
                lv.y = __float2bfloat16(v1 - __bfloat162float(h1));
                *(__nv_bfloat162*)&oh[(long)gm * Nd + gn] = hv;
                *(__nv_bfloat162*)&ol[(long)gm * Nd + gn] = lv;
            }
        }
    }
}

// ---------------- fused HMMA score kernel (cp.async loads) -------------------
__global__ __launch_bounds__(256, 2)
void score_mma(const __nv_bfloat16* __restrict__ qh, const __nv_bfloat16* __restrict__ ql,
               float* __restrict__ s) {
    extern __shared__ __align__(16) __nv_bfloat16 sms[];
    __nv_bfloat16* Qh = sms;
    __nv_bfloat16* Ql = sms + SC_TE;
    __nv_bfloat16* Kh = sms + 2 * SC_TE;
    __nv_bfloat16* Kl = sms + 3 * SC_TE;
    bool colmode = (blockIdx.x == 0);
    int b = blockIdx.z, yy = blockIdx.y;
    int tid = threadIdx.x, lane = tid & 31, wid = tid >> 5;
    int wm = wid >> 2, wn = wid & 3;
    const int rstr = colmode ? W : 1;
    long line0 = (long)b * P + (colmode ? yy : (long)yy * W);

    #pragma unroll
    for (int j = 0; j < 4; j++) {
        int idx = tid + j * 256;
        int r = idx >> 3, g8 = (idx & 7) * 8;
        bool ok = r < 97;
        long base = (line0 + (long)(ok ? r : 0) * rstr) * 128;
        cp16(smem_u32(Qh + r * 72 + g8), qh + base + g8,      ok);
        cp16(smem_u32(Ql + r * 72 + g8), ql + base + g8,      ok);
        cp16(smem_u32(Kh + r * 72 + g8), qh + base + 64 + g8, ok);
        cp16(smem_u32(Kl + r * 72 + g8), ql + base + 64 + g8, ok);
    }
    CP_COMMIT();
    CP_WAIT(0);
    __syncthreads();

    float acc[4][4][4];
    #pragma unroll
    for (int mt = 0; mt < 4; mt++)
        #pragma unroll
        for (int nt = 0; nt < 4; nt++)
            #pragma unroll
            for (int i = 0; i < 4; i++) acc[mt][nt][i] = 0.f;

    #pragma unroll
    for (int ck = 0; ck < 4; ck++) {
        int kk = ck * 16;
        uint32_t aH[4][4], aL[4][4], bH[4][2], bL[4][2];
        #pragma unroll
        for (int mt = 0; mt < 4; mt++) {
            int arow = wm * 64 + mt * 16 + (lane & 15);
            int acol = kk + ((lane >> 4) << 3);
            uint32_t ad = smem_u32(Qh + arow * 72 + acol);
            asm volatile("ldmatrix.sync.aligned.m8n8.x4.shared.b16 {%0,%1,%2,%3}, [%4];"
                : "=r"(aH[mt][0]), "=r"(aH[mt][1]), "=r"(aH[mt][2]), "=r"(aH[mt][3]) : "r"(ad));
            uint32_t ad2 = smem_u32(Ql + arow * 72 + acol);
            asm volatile("ldmatrix.sync.aligned.m8n8.x4.shared.b16 {%0,%1,%2,%3}, [%4];"
                : "=r"(aL[mt][0]), "=r"(aL[mt][1]), "=r"(aL[mt][2]), "=r"(aL[mt][3]) : "r"(ad2));
        }
        #pragma unroll
        for (int np = 0; np < 2; np++) {
            int q = lane >> 3;
            int brow = wn * 32 + np * 16 + ((q >> 1) << 3) + (lane & 7);
            int bcol = kk + ((q & 1) << 3);
            uint32_t r0, r1, r2, r3;
            uint32_t bd = smem_u32(Kh + brow * 72 + bcol);
            asm volatile("ldmatrix.sync.aligned.m8n8.x4.shared.b16 {%0,%1,%2,%3}, [%4];"
                : "=r"(r0), "=r"(r1), "=r"(r2), "=r"(r3) : "r"(bd));
            bH[np * 2][0] = r0; bH[np * 2][1] = r1;
            bH[np * 2 + 1][0] = r2; bH[np * 2 + 1][1] = r3;
            uint32_t bd2 = smem_u32(Kl + brow * 72 + bcol);
            asm volatile("ldmatrix.sync.aligned.m8n8.x4.shared.b16 {%0,%1,%2,%3}, [%4];"
                : "=r"(r0), "=r"(r1), "=r"(r2), "=r"(r3) : "r"(bd2));
            bL[np * 2][0] = r0; bL[np * 2][1] = r1;
            bL[np * 2 + 1][0] = r2; bL[np * 2 + 1][1] = r3;
        }
        #pragma unroll
        for (int mt = 0; mt < 4; mt++)
            #pragma unroll
            for (int nt = 0; nt < 4; nt++) {
                asm volatile("mma.sync.aligned.m16n8k16.row.col.f32.bf16.bf16.f32 "
                    "{%0,%1,%2,%3}, {%4,%5,%6,%7}, {%8,%9}, {%0,%1,%2,%3};"
                    : "+f"(acc[mt][nt][0]), "+f"(acc[mt][nt][1]),
                      "+f"(acc[mt][nt][2]), "+f"(acc[mt][nt][3])
                    : "r"(aH[mt][0]), "r"(aH[mt][1]), "r"(aH[mt][2]), "r"(aH[mt][3]),
                      "r"(bH[nt][0]), "r"(bH[nt][1]));
                asm volatile("mma.sync.aligned.m16n8k16.row.col.f32.bf16.bf16.f32 "
                    "{%0,%1,%2,%3}, {%4,%5,%6,%7}, {%8,%9}, {%0,%1,%2,%3};"
                    : "+f"(acc[mt][nt][0]), "+f"(acc[mt][nt][1]),
                      "+f"(acc[mt][nt][2]), "+f"(acc[mt][nt][3])
                    : "r"(aL[mt][0]), "r"(aL[mt][1]), "r"(aL[mt][2]), "r"(aL[mt][3]),
                      "r"(bH[nt][0]), "r"(bH[nt][1]));
                asm volatile("mma.sync.aligned.m16n8k16.row.col.f32.bf16.bf16.f32 "
                    "{%0,%1,%2,%3}, {%4,%5,%6,%7}, {%8,%9}, {%0,%1,%2,%3};"
                    : "+f"(acc[mt][nt][0]), "+f"(acc[mt][nt][1]),
                      "+f"(acc[mt][nt][2]), "+f"(acc[mt][nt][3])
                    : "r"(aH[mt][0]), "r"(aH[mt][1]), "r"(aH[mt][2]), "r"(aH[mt][3]),
                      "r"(bL[nt][0]), "r"(bL[nt][1]));
            }
    }

    #pragma unroll
    for (int mt = 0; mt < 4; mt++) {
        #pragma unroll
        for (int nt = 0; nt < 4; nt++) {
            int gn = wn * 32 + nt * 8 + 2 * (lane & 3);
            #pragma unroll
            for (int half = 0; half < 2; half++) {
                int r = wm * 64 + mt * 16 + (lane >> 2) + half * 8;
                if (r >= 97) continue;
                float* outp = s + (line0 + (long)r * rstr) * S + (colmode ? 0 : 97);
                float v0 = acc[mt][nt][half * 2];
                float v1 = acc[mt][nt][half * 2 + 1];
                if (colmode && r == gn)     v0 += NEG_INF;
                if (colmode && r == gn + 1) v1 += NEG_INF;
                if (gn < 97)     outp[gn]     = v0;
                if (gn + 1 < 97) outp[gn + 1] = v1;
            }
        }
    }
}

// ---------------- softmax ----------------------------------------------------
__global__ __launch_bounds__(256)
void softmax194(const float* __restrict__ s, __nv_bfloat16* __restrict__ sh,
                __nv_bfloat16* __restrict__ sl) {
    long row = (long)blockIdx.x * 8 + (threadIdx.x >> 5);
    int lane = threadIdx.x & 31;
    const float* r = s + row * S;
    float v[7];
    float m = -3.0e38f;
    #pragma unroll
    for (int t = 0; t < 7; t++) {
        int idx = lane + 32 * t;
        v[t] = (idx < S) ? r[idx] : -3.0e38f;
        m = fmaxf(m, v[t]);
    }
    #pragma unroll
    for (int o = 16; o > 0; o >>= 1) m = fmaxf(m, __shfl_xor_sync(0xffffffffu, m, o));
    float sum = 0.f;
    #pragma unroll
    for (int t = 0; t < 7; t++) { v[t] = __expf(v[t] - m); sum += v[t]; }
    #pragma unroll
    for (int o = 16; o > 0; o >>= 1) sum += __shfl_xor_sync(0xffffffffu, sum, o);
    float inv = 1.0f / sum;
    __nv_bfloat16* shr = sh + row * SP;
    __nv_bfloat16* slr = sl + row * SP;
    #pragma unroll
    for (int t = 0; t < 7; t++) {
        int idx = lane + 32 * t;
        if (idx < S) {
            float val = v[t] * inv;
            int o = idx < 97 ? idx : OFFW + (idx - 97);
            __nv_bfloat16 hi = __float2bfloat16(val);
            shr[o] = hi;
            slr[o] = __float2bfloat16(val - __bfloat162float(hi));
        }
    }
}

// ---------------- HMMA apply (round-12 shape) --------------------------------
template<bool COLMODE>
__global__ __launch_bounds__(256, 2)
void apply_mma(const __nv_bfloat16* __restrict__ sh, const __nv_bfloat16* __restrict__ sl,
               const __nv_bfloat16* __restrict__ vh, const __nv_bfloat16* __restrict__ vl,
               float* __restrict__ y, const float* __restrict__ x,
               const float* __restrict__ gamma, __nv_bfloat16* __restrict__ xs) {
    extern __shared__ __align__(16) __nv_bfloat16 sma[];
    __nv_bfloat16* Ah = sma;                 // [2][128][40]
    __nv_bfloat16* Al = sma + 2 * APT;
    __nv_bfloat16* Vh = sma + 4 * APT;       // [2][32][136]
    __nv_bfloat16* Vl = sma + 4 * APT + 2 * VPT;
    int b = blockIdx.z, yy = blockIdx.y, c0 = blockIdx.x * 128;
    int tid = threadIdx.x, lane = tid & 31, wid = tid >> 5;
    int wm = wid >> 2, wn = wid & 3;
    const int rstr = COLMODE ? W : 1;
    long line0 = (long)b * P + (COLMODE ? yy : (long)yy * W);
    const int off = COLMODE ? 0 : OFFW;

    float acc[4][4][4];
    #pragma unroll
    for (int mt = 0; mt < 4; mt++)
        #pragma unroll
        for (int nt = 0; nt < 4; nt++)
            #pragma unroll
            for (int i = 0; i < 4; i++) acc[mt][nt][i] = 0.f;

    auto load_chunk = [&](int ch, int buf) {
        int g0 = ch * 32;
        #pragma unroll
        for (int j = 0; j < 2; j++) {
            int idx = tid + j * 256;
            int r = idx >> 2, q = idx & 3;
            int gg = g0 + q * 8;
            int ab = (r < 97 && gg < 97) ? min(97 - gg, 8) * 2 : 0;
            long rowoff = (line0 + (long)(r < 97 ? r : 0) * rstr) * SP + off + (gg < 97 ? gg : 0);
            cp16v(smem_u32(Ah + buf * APT + r * 40 + q * 8), sh + rowoff, ab);
            cp16v(smem_u32(Al + buf * APT + r * 40 + q * 8), sl + rowoff, ab);
        }
        #pragma unroll
        for (int j = 0; j < 2; j++) {
            int idx = tid + j * 256;
            int g = idx >> 4, c8 = (idx & 15) * 8;
            int gabs = g0 + g;
            int vb = (gabs < 97) ? 16 : 0;
            long nk = (line0 + (long)(gabs < 97 ? gabs : 0) * rstr) * C + c0 + c8;
            cp16v(smem_u32(Vh + buf * VPT + g * 136 + c8), vh + nk, vb);
            cp16v(smem_u32(Vl + buf * VPT + g * 136 + c8), vl + nk, vb);
        }
        CP_COMMIT();
    };

    load_chunk(0, 0);
    for (int ch = 0; ch < 4; ch++) {
        int cur = ch & 1;
        if (ch + 1 < 4) {
            load_chunk(ch + 1, cur ^ 1);
            CP_WAIT(1);
        } else {
            CP_WAIT(0);
        }
        __syncthreads();
        #pragma unroll
        for (int ks = 0; ks < 2; ks++) {
            int kk = ks * 16;
            uint32_t aH[4][4], aL[4][4], bf[4][2];
            #pragma unroll
            for (int mt = 0; mt < 4; mt++) {
                int arow = wm * 64 + mt * 16 + (lane & 15);
                int acol = kk + ((lane >> 4) << 3);
                uint32_t ad = smem_u32(Ah + cur * APT + arow * 40 + acol);
                asm volatile("ldmatrix.sync.aligned.m8n8.x4.shared.b16 {%0,%1,%2,%3}, [%4];"
                    : "=r"(aH[mt][0]), "=r"(aH[mt][1]), "=r"(aH[mt][2]), "=r"(aH[mt][3]) : "r"(ad));
                uint32_t ad2 = smem_u32(Al + cur * APT + arow * 40 + acol);
                asm volatile("ldmatrix.sync.aligned.m8n8.x4.shared.b16 {%0,%1,%2,%3}, [%4];"
                    : "=r"(aL[mt][0]), "=r"(aL[mt][1]), "=r"(aL[mt][2]), "=r"(aL[mt][3]) : "r"(ad2));
            }
            #pragma unroll
            for (int np = 0; np < 2; np++) {
                int q = lane >> 3;
                int krow = kk + ((q & 1) << 3) + (lane & 7);
                int ncol = wn * 32 + np * 16 + ((q >> 1) << 3);
                uint32_t r0, r1, r2, r3;
                uint32_t bd = smem_u32(Vh + cur * VPT + krow * 136 + ncol);
                asm volatile("ldmatrix.sync.aligned.m8n8.x4.trans.shared.b16 {%0,%1,%2,%3}, [%4];"
                    : "=r"(r0), "=r"(r1), "=r"(r2), "=r"(r3) : "r"(bd));
                bf[np * 2][0] = r0; bf[np * 2][1] = r1;
                bf[np * 2 + 1][0] = r2; bf[np * 2 + 1][1] = r3;
            }
            #pragma unroll
            for (int mt = 0; mt < 4; mt++)
                #pragma unroll
                for (int nt = 0; nt < 4; nt++) {
                    asm volatile("mma.sync.aligned.m16n8k16.row.col.f32.bf16.bf16.f32 "
                        "{%0,%1,%2,%3}, {%4,%5,%6,%7}, {%8,%9}, {%0,%1,%2,%3};"
                        : "+f"(acc[mt][nt][0]), "+f"(acc[mt][nt][1]),
                          "+f"(acc[mt][nt][2]), "+f"(acc[mt][nt][3])
                        : "r"(aH[mt][0]), "r"(aH[mt][1]), "r"(aH[mt][2]), "r"(aH[mt][3]),
                          "r"(bf[nt][0]), "r"(bf[nt][1]));
                    asm volatile("mma.sync.aligned.m16n8k16.row.col.f32.bf16.bf16.f32 "
                        "{%0,%1,%2,%3}, {%4,%5,%6,%7}, {%8,%9}, {%0,%1,%2,%3};"
                        : "+f"(acc[mt][nt][0]), "+f"(acc[mt][nt][1]),
                          "+f"(acc[mt][nt][2]), "+f"(acc[mt][nt][3])
                        : "r"(aL[mt][0]), "r"(aL[mt][1]), "r"(aL[mt][2]), "r"(aL[mt][3]),
                          "r"(bf[nt][0]), "r"(bf[nt][1]));
                }
            #pragma unroll
            for (int np = 0; np < 2; np++) {
                int q = lane >> 3;
                int krow = kk + ((q & 1) << 3) + (lane & 7);
                int ncol = wn * 32 + np * 16 + ((q >> 1) << 3);
                uint32_t r0, r1, r2, r3;
                uint32_t bd = smem_u32(Vl + cur * VPT + krow * 136 + ncol);
                asm volatile("ldmatrix.sync.aligned.m8n8.x4.trans.shared.b16 {%0,%1,%2,%3}, [%4];"
                    : "=r"(r0), "=r"(r1), "=r"(r2), "=r"(r3) : "r"(bd));
                bf[np * 2][0] = r0; bf[np * 2][1] = r1;
                bf[np * 2 + 1][0] = r2; bf[np * 2 + 1][1] = r3;
            }
            #pragma unroll
            for (int mt = 0; mt < 4; mt++)
                #pragma unroll
                for (int nt = 0; nt < 4; nt++)
                    asm volatile("mma.sync.aligned.m16n8k16.row.col.f32.bf16.bf16.f32 "
                        "{%0,%1,%2,%3}, {%4,%5,%6,%7}, {%8,%9}, {%0,%1,%2,%3};"
                        : "+f"(acc[mt][nt][0]), "+f"(acc[mt][nt][1]),
                          "+f"(acc[mt][nt][2]), "+f"(acc[mt][nt][3])
                        : "r"(aH[mt][0]), "r"(aH[mt][1]), "r"(aH[mt][2]), "r"(aH[mt][3]),
                          "r"(bf[nt][0]), "r"(bf[nt][1]));
        }
        __syncthreads();
    }

    float gmv = COLMODE ? 0.f : __ldg(gamma);
    #pragma unroll
    for (int mt = 0; mt < 4; mt++) {
        #pragma unroll
        for (int nt = 0; nt < 4; nt++) {
            int gn = c0 + wn * 32 + nt * 8 + 2 * (lane & 3);
            #pragma unroll
            for (int half = 0; half < 2; half++) {
                int r = wm * 64 + mt * 16 + (lane >> 2) + half * 8;
                if (r >= 97) continue;
                long node = line0 + (long)r * rstr;
                long addr = node * C + gn;
                float a0 = acc[mt][nt][half * 2], a1 = acc[mt][nt][half * 2 + 1];
                if (COLMODE) {
                    float2 o; o.x = a0; o.y = a1;
                    *(float2*)&y[addr] = o;
                } else {
                    float2 p = *(const float2*)&y[addr];
                    float2 xx = *(const float2*)&x[addr];
                    float2 o;
                    o.x = gmv * (p.x + a0) + xx.x;
                    o.y = gmv * (p.y + a1) + xx.y;
                    *(float2*)&y[addr] = o;
                    if (xs) {
                        __nv_bfloat16 h0 = __float2bfloat16(o.x), h1 = __float2bfloat16(o.y);
                        __nv_bfloat162 hv; hv.x = h0; hv.y = h1;
                        __nv_bfloat162 lv;
                        lv.x = __float2bfloat16(o.x - __bfloat162float(h0));
                        lv.y = __float2bfloat16(o.y - __bfloat162float(h1));
                        *(__nv_bfloat162*)&xs[node * KA + gn]     = hv;
                        *(__nv_bfloat162*)&xs[node * KA + C + gn] = lv;
                    }
                }
            }
        }
    }
}

// ---------------- launch -----------------------------------------------------
extern "C" void kernel_launch(void* const* d_in, const int* in_sizes, int n_in,
                              void* d_out, int out_size) {
    const float* x     = (const float*)d_in[0];
    const float* Wq    = (const float*)d_in[1];
    const float* bq    = (const float*)d_in[2];
    const float* Wk    = (const float*)d_in[3];
    const float* bk    = (const float*)d_in[4];
    const float* Wv    = (const float*)d_in[5];
    const float* bv    = (const float*)d_in[6];
    const float* gamma = (const float*)d_in[7];
    float* out = (float*)d_out;

    float *xT, *yT, *sp, *bqk;
    __nv_bfloat16 *xs, *wsv, *wsqk, *sh, *sl, *vh, *vl, *qkh, *qkl;
    cudaGetSymbolAddress((void**)&xT,  g_xT);
    cudaGetSymbolAddress((void**)&yT,  g_yT);
    cudaGetSymbolAddress((void**)&sp,  g_s);
    cudaGetSymbolAddress((void**)&xs,   g_xs);
    cudaGetSymbolAddress((void**)&wsv,  g_wsv);
    cudaGetSymbolAddress((void**)&wsqk, g_wsqk);
    cudaGetSymbolAddress((void**)&bqk,  g_bqk);
    cudaGetSymbolAddress((void**)&sh,  g_sh);
    cudaGetSymbolAddress((void**)&sl,  g_sl);
    cudaGetSymbolAddress((void**)&vh,  g_vh);
    cudaGetSymbolAddress((void**)&vl,  g_vl);
    cudaGetSymbolAddress((void**)&qkh, g_qkh);
    cudaGetSymbolAddress((void**)&qkl, g_qkl);

    cudaFuncSetAttribute(mma_proj,  cudaFuncAttributeMaxDynamicSharedMemorySize, SMEM_PROJ);
    cudaFuncSetAttribute(score_mma, cudaFuncAttributeMaxDynamicSharedMemorySize, SMEM_SCORE);
    cudaFuncSetAttribute(apply_mma<true >, cudaFuncAttributeMaxDynamicSharedMemorySize, SMEM_APPLY);
    cudaFuncSetAttribute(apply_mma<false>, cudaFuncAttributeMaxDynamicSharedMemorySize, SMEM_APPLY);

    dim3 tgrid((P + 31) / 32, C / 32, B), tthr(32, 8);
    transpose_in<<<tgrid, tthr>>>(x, xT, xs);
    prep_w<<<320, 256>>>(Wq, Wk, Wv, bq, bk);

    for (int it = 0; it < 2; it++) {
        const float* X = it ? yT : xT;
        float*       Y = it ? xT : yT;
        mma_proj<<<dim3(5, MBLK), 256, SMEM_PROJ>>>(xs, wsqk, wsv, bqk, bv, qkh, qkl, vh, vl);
        score_mma<<<dim3(2, W, B), 256, SMEM_SCORE>>>(qkh, qkl, sp);
        softmax194<<<P, 256>>>(sp, sh, sl);
        apply_mma<true ><<<dim3(4, W, B), 256, SMEM_APPLY>>>(sh, sl, vh, vl, Y, X, gamma, nullptr);
        apply_mma<false><<<dim3(4, H, B), 256, SMEM_APPLY>>>(sh, sl, vh, vl, Y, X, gamma, it == 0 ? xs : nullptr);
    }

    transpose_out<<<tgrid, tthr>>>(xT, out);
}

// round 16
// speedup vs baseline: 1.2978x; 1.1849x over previous
#include <cuda_runtime.h>
#include <cuda_fp16.h>
#include <cstdint>

namespace {
constexpr int B   = 8;
constexpr int H   = 97;
constexpr int W   = 97;
constexpr int C   = 512;
constexpr int P   = H * W;        // 9409
constexpr int S   = H + W;        // 194
constexpr int BP  = B * P;        // 75272
constexpr int KA  = 2 * C;        // 1024: [hi | lo] storage
constexpr int NCH = 16;           // proj: 16 physical chunks of k32
constexpr int MBLK = (BP + 127) / 128;   // 589
constexpr int SP   = 224;         // padded attention row stride
constexpr int OFFW = 112;         // aW section offset within SP
constexpr int TILE_E = 128 * 40;  // proj smem tile elems
constexpr int SMEM_PROJ = 8 * TILE_E * 2;     // 81920 bytes
constexpr int SC_TE = 128 * 72;               // score tile elems
constexpr int SMEM_SCORE = 4 * SC_TE * 2;     // 73728 bytes
// apply: A hi/lo tiles 128x40 (2 stages), V single tiles 32x136 (2 stages)
constexpr int APT = 128 * 40;
constexpr int VPT = 32 * 136;
constexpr int SMEM_APPLY = (4 * APT + 2 * VPT) * 2;   // 58368 bytes
constexpr float NEG_INF = -1000000000.0f;
}

// ---------------- scratch ---------------------------------------------------
__device__ float g_xT[BP * C];
__device__ float g_yT[BP * C];
__device__ float g_s [BP * S];
__device__ __half g_qkh[(long)BP * 128];
__device__ __half g_qkl[(long)BP * 128];
__device__ __half g_sh[(long)BP * SP];
__device__ __half g_sl[(long)BP * SP];
__device__ __half g_vh[(long)BP * C];             // v single fp16
__device__ __half g_xs[(long)BP * KA];            // split x: [hi | lo]
__device__ __half g_wsv [C * C];                  // Wv single fp16
__device__ __half g_wsqk[128 * KA];               // split Wq|Wk: [hi | lo]
__device__ float g_bqk[128];

__device__ __forceinline__ uint32_t smem_u32(const void* p) {
    uint32_t a;
    asm("{ .reg .u64 t; cvta.to.shared.u64 t, %1; cvt.u32.u64 %0, t; }" : "=r"(a) : "l"(p));
    return a;
}
__device__ __forceinline__ void cp16(uint32_t dst, const void* src, bool valid) {
    int sz = valid ? 16 : 0;
    asm volatile("cp.async.cg.shared.global [%0], [%1], 16, %2;" :: "r"(dst), "l"(src), "r"(sz));
}
__device__ __forceinline__ void cp16v(uint32_t dst, const void* src, int bytes) {
    asm volatile("cp.async.cg.shared.global [%0], [%1], 16, %2;" :: "r"(dst), "l"(src), "r"(bytes));
}
#define CP_COMMIT() asm volatile("cp.async.commit_group;" ::: "memory")
#define CP_WAIT(n)  asm volatile("cp.async.wait_group %0;" :: "n"(n) : "memory")
#define MMA16816(acc, a, b) \
    asm volatile("mma.sync.aligned.m16n8k16.row.col.f32.f16.f16.f32 " \
        "{%0,%1,%2,%3}, {%4,%5,%6,%7}, {%8,%9}, {%0,%1,%2,%3};" \
        : "+f"((acc)[0]), "+f"((acc)[1]), "+f"((acc)[2]), "+f"((acc)[3]) \
        : "r"((a)[0]), "r"((a)[1]), "r"((a)[2]), "r"((a)[3]), \
          "r"((b)[0]), "r"((b)[1]))

__device__ __forceinline__ __half2 split_hi(float v0, float v1, __half2& lo) {
    __half h0 = __float2half(v0), h1 = __float2half(v1);
    lo = __halves2half2(__float2half(v0 - __half2float(h0)),
                        __float2half(v1 - __half2float(h1)));
    return __halves2half2(h0, h1);
}

// ---------------- transpose in: (B,C,P) -> (B,P,C) f32 + split fp16 ----------
__global__ void transpose_in(const float* __restrict__ src, float* __restrict__ dst,
                             __half* __restrict__ xs) {
    __shared__ float t[32][33];
    int b = blockIdx.z, n0 = blockIdx.x * 32, c0 = blockIdx.y * 32;
    const float* sp = src + (long)b * C * P;
    for (int i = threadIdx.y; i < 32; i += 8) {
        int n = n0 + threadIdx.x;
        if (n < P) t[i][threadIdx.x] = sp[(long)(c0 + i) * P + n];
    }
    __syncthreads();
    for (int i = threadIdx.y; i < 32; i += 8) {
        int n = n0 + i;
        if (n < P) {
            float v = t[threadIdx.x][i];
            long m = (long)b * P + n;
            dst[m * C + c0 + threadIdx.x] = v;
            __half hv = __float2half(v);
            xs[m * KA + c0 + threadIdx.x]     = hv;
            xs[m * KA + C + c0 + threadIdx.x] = __float2half(v - __half2float(hv));
        }
    }
}
__global__ void transpose_out(const float* __restrict__ src, float* __restrict__ dst) {
    __shared__ float t[32][33];
    int b = blockIdx.z, n0 = blockIdx.x * 32, c0 = blockIdx.y * 32;
    const float* sp = src + (long)b * P * C;
    float*       dp = dst + (long)b * C * P;
    for (int i = threadIdx.y; i < 32; i += 8) {
        int n = n0 + i;
        if (n < P) t[i][threadIdx.x] = sp[(long)n * C + c0 + threadIdx.x];
    }
    __syncthreads();
    for (int i = threadIdx.y; i < 32; i += 8) {
        int n = n0 + threadIdx.x;
        if (n < P) dp[(long)(c0 + i) * P + n] = t[threadIdx.x][i];
    }
}

__global__ __launch_bounds__(256) void prep_w(const float* __restrict__ Wq, const float* __restrict__ Wk,
                                              const float* __restrict__ Wv, const float* __restrict__ bq,
                                              const float* __restrict__ bk) {
    int i = blockIdx.x * 256 + threadIdx.x;
    if (blockIdx.x == 0 && threadIdx.x < 128)
        g_bqk[threadIdx.x] = threadIdx.x < 64 ? bq[threadIdx.x] : bk[threadIdx.x - 64];
    if (i >= 640 * 128) return;
    int r = i >> 7, c4 = (i & 127) * 4;
    if (r < 512) {
        // Wv: single fp16
        float4 x = *(const float4*)&Wv[(long)r * C + c4];
        __half* dst = g_wsv + (long)r * C;
        *(__half2*)&dst[c4]     = __halves2half2(__float2half(x.x), __float2half(x.y));
        *(__half2*)&dst[c4 + 2] = __halves2half2(__float2half(x.z), __float2half(x.w));
    } else {
        int rr = r - 512;
        const float* src = (rr < 64 ? Wq + (long)rr * C : Wk + (long)(rr - 64) * C) + c4;
        __half* dst = g_wsqk + (long)rr * KA;
        float4 x = *(const float4*)src;
        __half2 l01, l23;
        __half2 h01 = split_hi(x.x, x.y, l01);
        __half2 h23 = split_hi(x.z, x.w, l23);
        *(__half2*)&dst[c4]         = h01; *(__half2*)&dst[c4 + 2]     = h23;
        *(__half2*)&dst[C + c4]     = l01; *(__half2*)&dst[C + c4 + 2] = l23;
    }
}

// ---------------- fused HMMA projection GEMM (qk 3-prod + v 2-prod) ----------
__global__ __launch_bounds__(256, 2)
void mma_proj(const __half* __restrict__ A,
              const __half* __restrict__ wqk, const __half* __restrict__ wv,
              const float* __restrict__ bqk_, const float* __restrict__ bv_,
              __half* __restrict__ qkh, __half* __restrict__ qkl,
              __half* __restrict__ vvh) {
    extern __shared__ __align__(16) __half smp[];
    int tid = threadIdx.x, lane = tid & 31, wid = tid >> 5;
    int wm = wid >> 2, wn = wid & 3;
    int row0 = blockIdx.y * 128;
    bool isqk = (blockIdx.x == 4);
    int col0 = isqk ? 0 : blockIdx.x * 128;

    auto tile = [&](int buf, int t) -> __half* {
        return smp + (buf * 4 + t) * TILE_E;
    };

    float acc[4][4][4];
    #pragma unroll
    for (int mt = 0; mt < 4; mt++)
        #pragma unroll
        for (int nt = 0; nt < 4; nt++)
            #pragma unroll
            for (int i = 0; i < 4; i++) acc[mt][nt][i] = 0.f;

    auto load_chunk = [&](int ch, int buf) {
        int kin = ch * 32;
        #pragma unroll
        for (int j = 0; j < 2; j++) {
            int g = tid + j * 256;
            int m = g >> 2, q = g & 3;
            int gm = row0 + m;
            bool ok = gm < BP;
            const __half* abase = A + (long)(ok ? gm : 0) * KA + kin + q * 8;
            cp16(smem_u32(tile(buf, 0) + m * 40 + q * 8), abase, ok);
            cp16(smem_u32(tile(buf, 1) + m * 40 + q * 8), abase + C, ok);
            if (isqk) {
                const __half* bbase = wqk + (long)(col0 + m) * KA + kin + q * 8;
                cp16(smem_u32(tile(buf, 2) + m * 40 + q * 8), bbase, true);
                cp16(smem_u32(tile(buf, 3) + m * 40 + q * 8), bbase + C, true);
            } else {
                const __half* bbase = wv + (long)(col0 + m) * C + kin + q * 8;
                cp16(smem_u32(tile(buf, 2) + m * 40 + q * 8), bbase, true);
            }
        }
        CP_COMMIT();
    };

    load_chunk(0, 0);
    for (int ch = 0; ch < NCH; ch++) {
        int buf = ch & 1;
        if (ch + 1 < NCH) {
            load_chunk(ch + 1, buf ^ 1);
            CP_WAIT(1);
        } else {
            CP_WAIT(0);
        }
        __syncthreads();
        #pragma unroll
        for (int ks = 0; ks < 2; ks++) {
            int kk = ks * 16;
            uint32_t aH[4][4], aL[4][4], bf[4][2];
            #pragma unroll
            for (int mt = 0; mt < 4; mt++) {
                int arow = wm * 64 + mt * 16 + (lane & 15);
                int acol = kk + ((lane >> 4) << 3);
                uint32_t ad = smem_u32(tile(buf, 0) + arow * 40 + acol);
                asm volatile("ldmatrix.sync.aligned.m8n8.x4.shared.b16 {%0,%1,%2,%3}, [%4];"
                    : "=r"(aH[mt][0]), "=r"(aH[mt][1]), "=r"(aH[mt][2]), "=r"(aH[mt][3]) : "r"(ad));
                uint32_t ad2 = smem_u32(tile(buf, 1) + arow * 40 + acol);
                asm volatile("ldmatrix.sync.aligned.m8n8.x4.shared.b16 {%0,%1,%2,%3}, [%4];"
                    : "=r"(aL[mt][0]), "=r"(aL[mt][1]), "=r"(aL[mt][2]), "=r"(aL[mt][3]) : "r"(ad2));
            }
            #pragma unroll
            for (int np = 0; np < 2; np++) {
                int q = lane >> 3;
                int brow = wn * 32 + np * 16 + ((q >> 1) << 3) + (lane & 7);
                int bcol = kk + ((q & 1) << 3);
                uint32_t bd = smem_u32(tile(buf, 2) + brow * 40 + bcol);
                uint32_t r0, r1, r2, r3;
                asm volatile("ldmatrix.sync.aligned.m8n8.x4.shared.b16 {%0,%1,%2,%3}, [%4];"
                    : "=r"(r0), "=r"(r1), "=r"(r2), "=r"(r3) : "r"(bd));
                bf[np * 2][0] = r0; bf[np * 2][1] = r1;
                bf[np * 2 + 1][0] = r2; bf[np * 2 + 1][1] = r3;
            }
            #pragma unroll
            for (int mt = 0; mt < 4; mt++)
                #pragma unroll
                for (int nt = 0; nt < 4; nt++) {
                    MMA16816(acc[mt][nt], aH[mt], bf[nt]);
                    MMA16816(acc[mt][nt], aL[mt], bf[nt]);
                }
            if (isqk) {
                #pragma unroll
                for (int np = 0; np < 2; np++) {
                    int q = lane >> 3;
                    int brow = wn * 32 + np * 16 + ((q >> 1) << 3) + (lane & 7);
                    int bcol = kk + ((q & 1) << 3);
                    uint32_t bd = smem_u32(tile(buf, 3) + brow * 40 + bcol);
                    uint32_t r0, r1, r2, r3;
                    asm volatile("ldmatrix.sync.aligned.m8n8.x4.shared.b16 {%0,%1,%2,%3}, [%4];"
                        : "=r"(r0), "=r"(r1), "=r"(r2), "=r"(r3) : "r"(bd));
                    bf[np * 2][0] = r0; bf[np * 2][1] = r1;
                    bf[np * 2 + 1][0] = r2; bf[np * 2 + 1][1] = r3;
                }
                #pragma unroll
                for (int mt = 0; mt < 4; mt++)
                    #pragma unroll
                    for (int nt = 0; nt < 4; nt++)
                        MMA16816(acc[mt][nt], aH[mt], bf[nt]);
            }
        }
        __syncthreads();
    }

    const float* bias = isqk ? bqk_ : bv_;
    int Nd = isqk ? 128 : 512;
    #pragma unroll
    for (int mt = 0; mt < 4; mt++) {
        #pragma unroll
        for (int nt = 0; nt < 4; nt++) {
            int gn = col0 + wn * 32 + nt * 8 + 2 * (lane & 3);
            float b0 = bias[gn], b1 = bias[gn + 1];
            #pragma unroll
            for (int half = 0; half < 2; half++) {
                int gm = row0 + wm * 64 + mt * 16 + (lane >> 2) + half * 8;
                if (gm >= BP) continue;
                float v0 = acc[mt][nt][half * 2] + b0;
                float v1 = acc[mt][nt][half * 2 + 1] + b1;
                if (isqk) {
                    __half2 lv;
                    __half2 hv = split_hi(v0, v1, lv);
                    *(__half2*)&qkh[(long)gm * Nd + gn] = hv;
                    *(__half2*)&qkl[(long)gm * Nd + gn] = lv;
                } else {
                    *(__half2*)&vvh[(long)gm * Nd + gn] =
                        __halves2half2(__float2half(v0), __float2half(v1));
                }
            }
        }
    }
}

// ---------------- fused HMMA score kernel (fp16, 3-product) ------------------
__global__ __launch_bounds__(256, 2)
void score_mma(const __half* __restrict__ qh, const __half* __restrict__ ql,
               float* __restrict__ s) {
    extern __shared__ __align__(16) __half sms[];
    __half* Qh = sms;
    __half* Ql = sms + SC_TE;
    __half* Kh = sms + 2 * SC_TE;
    __half* Kl = sms + 3 * SC_TE;
    bool colmode = (blockIdx.x == 0);
    int b = blockIdx.z, yy = blockIdx.y;
    int tid = threadIdx.x, lane = tid & 31, wid = tid >> 5;
    int wm = wid >> 2, wn = wid & 3;
    const int rstr = colmode ? W : 1;
    long line0 = (long)b * P + (colmode ? yy : (long)yy * W);

    #pragma unroll
    for (int j = 0; j < 4; j++) {
        int idx = tid + j * 256;
        int r = idx >> 3, g8 = (idx & 7) * 8;
        bool ok = r < 97;
        long base = (line0 + (long)(ok ? r : 0) * rstr) * 128;
        cp16(smem_u32(Qh + r * 72 + g8), qh + base + g8,      ok);
        cp16(smem_u32(Ql + r * 72 + g8), ql + base + g8,      ok);
        cp16(smem_u32(Kh + r * 72 + g8), qh + base + 64 + g8, ok);
        cp16(smem_u32(Kl + r * 72 + g8), ql + base + 64 + g8, ok);
    }
    CP_COMMIT();
    CP_WAIT(0);
    __syncthreads();

    float acc[4][4][4];
    #pragma unroll
    for (int mt = 0; mt < 4; mt++)
        #pragma unroll
        for (int nt = 0; nt < 4; nt++)
            #pragma unroll
            for (int i = 0; i < 4; i++) acc[mt][nt][i] = 0.f;

    #pragma unroll
    for (int ck = 0; ck < 4; ck++) {
        int kk = ck * 16;
        uint32_t aH[4][4], aL[4][4], bH[4][2], bL[4][2];
        #pragma unroll
        for (int mt = 0; mt < 4; mt++) {
            int arow = wm * 64 + mt * 16 + (lane & 15);
            int acol = kk + ((lane >> 4) << 3);
            uint32_t ad = smem_u32(Qh + arow * 72 + acol);
            asm volatile("ldmatrix.sync.aligned.m8n8.x4.shared.b16 {%0,%1,%2,%3}, [%4];"
                : "=r"(aH[mt][0]), "=r"(aH[mt][1]), "=r"(aH[mt][2]), "=r"(aH[mt][3]) : "r"(ad));
            uint32_t ad2 = smem_u32(Ql + arow * 72 + acol);
            asm volatile("ldmatrix.sync.aligned.m8n8.x4.shared.b16 {%0,%1,%2,%3}, [%4];"
                : "=r"(aL[mt][0]), "=r"(aL[mt][1]), "=r"(aL[mt][2]), "=r"(aL[mt][3]) : "r"(ad2));
        }
        #pragma unroll
        for (int np = 0; np < 2; np++) {
            int q = lane >> 3;
            int brow = wn * 32 + np * 16 + ((q >> 1) << 3) + (lane & 7);
            int bcol = kk + ((q & 1) << 3);
            uint32_t r0, r1, r2, r3;
            uint32_t bd = smem_u32(Kh + brow * 72 + bcol);
            asm volatile("ldmatrix.sync.aligned.m8n8.x4.shared.b16 {%0,%1,%2,%3}, [%4];"
                : "=r"(r0), "=r"(r1), "=r"(r2), "=r"(r3) : "r"(bd));
            bH[np * 2][0] = r0; bH[np * 2][1] = r1;
            bH[np * 2 + 1][0] = r2; bH[np * 2 + 1][1] = r3;
            uint32_t bd2 = smem_u32(Kl + brow * 72 + bcol);
            asm volatile("ldmatrix.sync.aligned.m8n8.x4.shared.b16 {%0,%1,%2,%3}, [%4];"
                : "=r"(r0), "=r"(r1), "=r"(r2), "=r"(r3) : "r"(bd2));
            bL[np * 2][0] = r0; bL[np * 2][1] = r1;
            bL[np * 2 + 1][0] = r2; bL[np * 2 + 1][1] = r3;
        }
        #pragma unroll
        for (int mt = 0; mt < 4; mt++)
            #pragma unroll
            for (int nt = 0; nt < 4; nt++) {
                MMA16816(acc[mt][nt], aH[mt], bH[nt]);
                MMA16816(acc[mt][nt], aL[mt], bH[nt]);
                MMA16816(acc[mt][nt], aH[mt], bL[nt]);
            }
    }

    #pragma unroll
    for (int mt = 0; mt < 4; mt++) {
        #pragma unroll
        for (int nt = 0; nt < 4; nt++) {
            int gn = wn * 32 + nt * 8 + 2 * (lane & 3);
            #pragma unroll
            for (int half = 0; half < 2; half++) {
                int r = wm * 64 + mt * 16 + (lane >> 2) + half * 8;
                if (r >= 97) continue;
                float* outp = s + (line0 + (long)r * rstr) * S + (colmode ? 0 : 97);
                float v0 = acc[mt][nt][half * 2];
                float v1 = acc[mt][nt][half * 2 + 1];
                if (colmode && r == gn)     v0 += NEG_INF;
                if (colmode && r == gn + 1) v1 += NEG_INF;
                if (gn < 97)     outp[gn]     = v0;
                if (gn + 1 < 97) outp[gn + 1] = v1;
            }
        }
    }
}

// ---------------- softmax: f32 scores -> fp16 hi/lo attention ----------------
__global__ __launch_bounds__(256)
void softmax194(const float* __restrict__ s, __half* __restrict__ sh,
                __half* __restrict__ sl) {
    long row = (long)blockIdx.x * 8 + (threadIdx.x >> 5);
    int lane = threadIdx.x & 31;
    const float* r = s + row * S;
    float v[7];
    float m = -3.0e38f;
    #pragma unroll
    for (int t = 0; t < 7; t++) {
        int idx = lane + 32 * t;
        v[t] = (idx < S) ? r[idx] : -3.0e38f;
        m = fmaxf(m, v[t]);
    }
    #pragma unroll
    for (int o = 16; o > 0; o >>= 1) m = fmaxf(m, __shfl_xor_sync(0xffffffffu, m, o));
    float sum = 0.f;
    #pragma unroll
    for (int t = 0; t < 7; t++) { v[t] = __expf(v[t] - m); sum += v[t]; }
    #pragma unroll
    for (int o = 16; o > 0; o >>= 1) sum += __shfl_xor_sync(0xffffffffu, sum, o);
    float inv = 1.0f / sum;
    __half* shr = sh + row * SP;
    __half* slr = sl + row * SP;
    #pragma unroll
    for (int t = 0; t < 7; t++) {
        int idx = lane + 32 * t;
        if (idx < S) {
            float val = v[t] * inv;
            int o = idx < 97 ? idx : OFFW + (idx - 97);
            __half hi = __float2half(val);
            shr[o] = hi;
            slr[o] = __float2half(val - __half2float(hi));
        }
    }
}

// ---------------- HMMA apply: A hi/lo, V single fp16, 2 products -------------
template<bool COLMODE>
__global__ __launch_bounds__(256, 2)
void apply_mma(const __half* __restrict__ sh, const __half* __restrict__ sl,
               const __half* __restrict__ vh,
               float* __restrict__ y, const float* __restrict__ x,
               const float* __restrict__ gamma, __half* __restrict__ xs) {
    extern __shared__ __align__(16) __half sma[];
    __half* Ah = sma;                 // [2][128][40]
    __half* Al = sma + 2 * APT;
    __half* Vh = sma + 4 * APT;       // [2][32][136]
    int b = blockIdx.z, yy = blockIdx.y, c0 = blockIdx.x * 128;
    int tid = threadIdx.x, lane = tid & 31, wid = tid >> 5;
    int wm = wid >> 2, wn = wid & 3;
    const int rstr = COLMODE ? W : 1;
    long line0 = (long)b * P + (COLMODE ? yy : (long)yy * W);
    const int off = COLMODE ? 0 : OFFW;

    float acc[4][4][4];
    #pragma unroll
    for (int mt = 0; mt < 4; mt++)
        #pragma unroll
        for (int nt = 0; nt < 4; nt++)
            #pragma unroll
            for (int i = 0; i < 4; i++) acc[mt][nt][i] = 0.f;

    auto load_chunk = [&](int ch, int buf) {
        int g0 = ch * 32;
        #pragma unroll
        for (int j = 0; j < 2; j++) {
            int idx = tid + j * 256;
            int r = idx >> 2, q = idx & 3;
            int gg = g0 + q * 8;
            int ab = (r < 97 && gg < 97) ? min(97 - gg, 8) * 2 : 0;
            long rowoff = (line0 + (long)(r < 97 ? r : 0) * rstr) * SP + off + (gg < 97 ? gg : 0);
            cp16v(smem_u32(Ah + buf * APT + r * 40 + q * 8), sh + rowoff, ab);
            cp16v(smem_u32(Al + buf * APT + r * 40 + q * 8), sl + rowoff, ab);
        }
        #pragma unroll
        for (int j = 0; j < 2; j++) {
            int idx = tid + j * 256;
            int g = idx >> 4, c8 = (idx & 15) * 8;
            int gabs = g0 + g;
            int vb = (gabs < 97) ? 16 : 0;
            long nk = (line0 + (long)(gabs < 97 ? gabs : 0) * rstr) * C + c0 + c8;
            cp16v(smem_u32(Vh + buf * VPT + g * 136 + c8), vh + nk, vb);
        }
        CP_COMMIT();
    };

    load_chunk(0, 0);
    for (int ch = 0; ch < 4; ch++) {
        int cur = ch & 1;
        if (ch + 1 < 4) {
            load_chunk(ch + 1, cur ^ 1);
            CP_WAIT(1);
        } else {
            CP_WAIT(0);
        }
        __syncthreads();
        #pragma unroll
        for (int ks = 0; ks < 2; ks++) {
            int kk = ks * 16;
            uint32_t aH[4][4], aL[4][4], bf[4][2];
            #pragma unroll
            for (int mt = 0; mt < 4; mt++) {
                int arow = wm * 64 + mt * 16 + (lane & 15);
                int acol = kk + ((lane >> 4) << 3);
                uint32_t ad = smem_u32(Ah + cur * APT + arow * 40 + acol);
                asm volatile("ldmatrix.sync.aligned.m8n8.x4.shared.b16 {%0,%1,%2,%3}, [%4];"
                    : "=r"(aH[mt][0]), "=r"(aH[mt][1]), "=r"(aH[mt][2]), "=r"(aH[mt][3]) : "r"(ad));
                uint32_t ad2 = smem_u32(Al + cur * APT + arow * 40 + acol);
                asm volatile("ldmatrix.sync.aligned.m8n8.x4.shared.b16 {%0,%1,%2,%3}, [%4];"
                    : "=r"(aL[mt][0]), "=r"(aL[mt][1]), "=r"(aL[mt][2]), "=r"(aL[mt][3]) : "r"(ad2));
            }
            #pragma unroll
            for (int np = 0; np < 2; np++) {
                int q = lane >> 3;
                int krow = kk + ((q & 1) << 3) + (lane & 7);
                int ncol = wn * 32 + np * 16 + ((q >> 1) << 3);
                uint32_t r0, r1, r2, r3;
                uint32_t bd = smem_u32(Vh + cur * VPT + krow * 136 + ncol);
                asm volatile("ldmatrix.sync.aligned.m8n8.x4.trans.shared.b16 {%0,%1,%2,%3}, [%4];"
                    : "=r"(r0), "=r"(r1), "=r"(r2), "=r"(r3) : "r"(bd));
                bf[np * 2][0] = r0; bf[np * 2][1] = r1;
                bf[np * 2 + 1][0] = r2; bf[np * 2 + 1][1] = r3;
            }
            #pragma unroll
            for (int mt = 0; mt < 4; mt++)
                #pragma unroll
                for (int nt = 0; nt < 4; nt++) {
                    MMA16816(acc[mt][nt], aH[mt], bf[nt]);
                    MMA16816(acc[mt][nt], aL[mt], bf[nt]);
                }
        }
        __syncthreads();
    }

    float gmv = COLMODE ? 0.f : __ldg(gamma);
    #pragma unroll
    for (int mt = 0; mt < 4; mt++) {
        #pragma unroll
        for (int nt = 0; nt < 4; nt++) {
            int gn = c0 + wn * 32 + nt * 8 + 2 * (lane & 3);
            #pragma unroll
            for (int half = 0; half < 2; half++) {
                int r = wm * 64 + mt * 16 + (lane >> 2) + half * 8;
                if (r >= 97) continue;
                long node = line0 + (long)r * rstr;
                long addr = node * C + gn;
                float a0 = acc[mt][nt][half * 2], a1 = acc[mt][nt][half * 2 + 1];
                if (COLMODE) {
                    float2 o; o.x = a0; o.y = a1;
                    *(float2*)&y[addr] = o;
                } else {
                    float2 p = *(const float2*)&y[addr];
                    float2 xx = *(const float2*)&x[addr];
                    float2 o;
                    o.x = gmv * (p.x + a0) + xx.x;
                    o.y = gmv * (p.y + a1) + xx.y;
                    *(float2*)&y[addr] = o;
                    if (xs) {
                        __half2 lv;
                        __half2 hv = split_hi(o.x, o.y, lv);
                        *(__half2*)&xs[node * KA + gn]     = hv;
                        *(__half2*)&xs[node * KA + C + gn] = lv;
                    }
                }
            }
        }
    }
}

// ---------------- launch -----------------------------------------------------
extern "C" void kernel_launch(void* const* d_in, const int* in_sizes, int n_in,
                              void* d_out, int out_size) {
    const float* x     = (const float*)d_in[0];
    const float* Wq    = (const float*)d_in[1];
    const float* bq    = (const float*)d_in[2];
    const float* Wk    = (const float*)d_in[3];
    const float* bk    = (const float*)d_in[4];
    const float* Wv    = (const float*)d_in[5];
    const float* bv    = (const float*)d_in[6];
    const float* gamma = (const float*)d_in[7];
    float* out = (float*)d_out;

    float *xT, *yT, *sp, *bqk;
    __half *xs, *wsv, *wsqk, *sh, *sl, *vh, *qkh, *qkl;
    cudaGetSymbolAddress((void**)&xT,  g_xT);
    cudaGetSymbolAddress((void**)&yT,  g_yT);
    cudaGetSymbolAddress((void**)&sp,  g_s);
    cudaGetSymbolAddress((void**)&xs,   g_xs);
    cudaGetSymbolAddress((void**)&wsv,  g_wsv);
    cudaGetSymbolAddress((void**)&wsqk, g_wsqk);
    cudaGetSymbolAddress((void**)&bqk,  g_bqk);
    cudaGetSymbolAddress((void**)&sh,  g_sh);
    cudaGetSymbolAddress((void**)&sl,  g_sl);
    cudaGetSymbolAddress((void**)&vh,  g_vh);
    cudaGetSymbolAddress((void**)&qkh, g_qkh);
    cudaGetSymbolAddress((void**)&qkl, g_qkl);

    cudaFuncSetAttribute(mma_proj,  cudaFuncAttributeMaxDynamicSharedMemorySize, SMEM_PROJ);
    cudaFuncSetAttribute(score_mma, cudaFuncAttributeMaxDynamicSharedMemorySize, SMEM_SCORE);
    cudaFuncSetAttribute(apply_mma<true >, cudaFuncAttributeMaxDynamicSharedMemorySize, SMEM_APPLY);
    cudaFuncSetAttribute(apply_mma<false>, cudaFuncAttributeMaxDynamicSharedMemorySize, SMEM_APPLY);

    dim3 tgrid((P + 31) / 32, C / 32, B), tthr(32, 8);
    transpose_in<<<tgrid, tthr>>>(x, xT, xs);
    prep_w<<<320, 256>>>(Wq, Wk, Wv, bq, bk);

    for (int it = 0; it < 2; it++) {
        const float* X = it ? yT : xT;
        float*       Y = it ? xT : yT;
        mma_proj<<<dim3(5, MBLK), 256, SMEM_PROJ>>>(xs, wsqk, wsv, bqk, bv, qkh, qkl, vh);
        score_mma<<<dim3(2, W, B), 256, SMEM_SCORE>>>(qkh, qkl, sp);
        softmax194<<<P, 256>>>(sp, sh, sl);
        apply_mma<true ><<<dim3(4, W, B), 256, SMEM_APPLY>>>(sh, sl, vh, Y, X, gamma, nullptr);
        apply_mma<false><<<dim3(4, H, B), 256, SMEM_APPLY>>>(sh, sl, vh, Y, X, gamma, it == 0 ? xs : nullptr);
    }

    transpose_out<<<tgrid, tthr>>>(xT, out);
}

// round 17
// speedup vs baseline: 1.3784x; 1.0621x over previous
#include <cuda_runtime.h>
#include <cuda_fp16.h>
#include <cstdint>

namespace {
constexpr int B   = 8;
constexpr int H   = 97;
constexpr int W   = 97;
constexpr int C   = 512;
constexpr int P   = H * W;        // 9409
constexpr int S   = H + W;        // 194
constexpr int BP  = B * P;        // 75272
constexpr int KA  = 2 * C;        // 1024: [hi | lo] storage
constexpr int NCH = 16;           // proj: 16 physical chunks of k32
constexpr int MBLK = (BP + 127) / 128;   // 589
constexpr int SP   = 224;         // padded attention row stride
constexpr int OFFW = 112;         // aW section offset within SP
constexpr int TILE_E = 128 * 40;  // proj smem tile elems
constexpr int SMEM_PROJ = 8 * TILE_E * 2;     // 81920 bytes
constexpr int SC_TE = 128 * 72;               // score tile elems
constexpr int SMEM_SCORE = 4 * SC_TE * 2;     // 73728 bytes
// apply: A hi tiles 128x40 (2 stages), V single tiles 32x136 (2 stages)
constexpr int APT = 128 * 40;
constexpr int VPT = 32 * 136;
constexpr int SMEM_APPLY = (2 * APT + 2 * VPT) * 2;   // 37888 bytes
constexpr float NEG_INF = -1000000000.0f;
}

// ---------------- scratch ---------------------------------------------------
__device__ float g_xT[BP * C];
__device__ float g_yT[BP * C];
__device__ float g_s [BP * S];
__device__ __half g_qkh[(long)BP * 128];
__device__ __half g_qkl[(long)BP * 128];
__device__ __half g_sh[(long)BP * SP];            // attention weights (hi only)
__device__ __half g_vh[(long)BP * C];             // v single fp16
__device__ __half g_xs[(long)BP * KA];            // split x: [hi | lo]
__device__ __half g_wsv [C * C];                  // Wv single fp16
__device__ __half g_wsqk[128 * KA];               // split Wq|Wk: [hi | lo]
__device__ float g_bqk[128];

__device__ __forceinline__ uint32_t smem_u32(const void* p) {
    uint32_t a;
    asm("{ .reg .u64 t; cvta.to.shared.u64 t, %1; cvt.u32.u64 %0, t; }" : "=r"(a) : "l"(p));
    return a;
}
__device__ __forceinline__ void cp16(uint32_t dst, const void* src, bool valid) {
    int sz = valid ? 16 : 0;
    asm volatile("cp.async.cg.shared.global [%0], [%1], 16, %2;" :: "r"(dst), "l"(src), "r"(sz));
}
__device__ __forceinline__ void cp16v(uint32_t dst, const void* src, int bytes) {
    asm volatile("cp.async.cg.shared.global [%0], [%1], 16, %2;" :: "r"(dst), "l"(src), "r"(bytes));
}
#define CP_COMMIT() asm volatile("cp.async.commit_group;" ::: "memory")
#define CP_WAIT(n)  asm volatile("cp.async.wait_group %0;" :: "n"(n) : "memory")
#define MMA16816(acc, a, b) \
    asm volatile("mma.sync.aligned.m16n8k16.row.col.f32.f16.f16.f32 " \
        "{%0,%1,%2,%3}, {%4,%5,%6,%7}, {%8,%9}, {%0,%1,%2,%3};" \
        : "+f"((acc)[0]), "+f"((acc)[1]), "+f"((acc)[2]), "+f"((acc)[3]) \
        : "r"((a)[0]), "r"((a)[1]), "r"((a)[2]), "r"((a)[3]), \
          "r"((b)[0]), "r"((b)[1]))

__device__ __forceinline__ __half2 split_hi(float v0, float v1, __half2& lo) {
    __half h0 = __float2half(v0), h1 = __float2half(v1);
    lo = __halves2half2(__float2half(v0 - __half2float(h0)),
                        __float2half(v1 - __half2float(h1)));
    return __halves2half2(h0, h1);
}

// ---------------- transpose in: (B,C,P) -> (B,P,C) f32 + split fp16 ----------
__global__ void transpose_in(const float* __restrict__ src, float* __restrict__ dst,
                             __half* __restrict__ xs) {
    __shared__ float t[32][33];
    int b = blockIdx.z, n0 = blockIdx.x * 32, c0 = blockIdx.y * 32;
    const float* sp = src + (long)b * C * P;
    for (int i = threadIdx.y; i < 32; i += 8) {
        int n = n0 + threadIdx.x;
        if (n < P) t[i][threadIdx.x] = sp[(long)(c0 + i) * P + n];
    }
    __syncthreads();
    for (int i = threadIdx.y; i < 32; i += 8) {
        int n = n0 + i;
        if (n < P) {
            float v = t[threadIdx.x][i];
            long m = (long)b * P + n;
            dst[m * C + c0 + threadIdx.x] = v;
            __half hv = __float2half(v);
            xs[m * KA + c0 + threadIdx.x]     = hv;
            xs[m * KA + C + c0 + threadIdx.x] = __float2half(v - __half2float(hv));
        }
    }
}
__global__ void transpose_out(const float* __restrict__ src, float* __restrict__ dst) {
    __shared__ float t[32][33];
    int b = blockIdx.z, n0 = blockIdx.x * 32, c0 = blockIdx.y * 32;
    const float* sp = src + (long)b * P * C;
    float*       dp = dst + (long)b * C * P;
    for (int i = threadIdx.y; i < 32; i += 8) {
        int n = n0 + i;
        if (n < P) t[i][threadIdx.x] = sp[(long)n * C + c0 + threadIdx.x];
    }
    __syncthreads();
    for (int i = threadIdx.y; i < 32; i += 8) {
        int n = n0 + threadIdx.x;
        if (n < P) dp[(long)(c0 + i) * P + n] = t[threadIdx.x][i];
    }
}

__global__ __launch_bounds__(256) void prep_w(const float* __restrict__ Wq, const float* __restrict__ Wk,
                                              const float* __restrict__ Wv, const float* __restrict__ bq,
                                              const float* __restrict__ bk) {
    int i = blockIdx.x * 256 + threadIdx.x;
    if (blockIdx.x == 0 && threadIdx.x < 128)
        g_bqk[threadIdx.x] = threadIdx.x < 64 ? bq[threadIdx.x] : bk[threadIdx.x - 64];
    if (i >= 640 * 128) return;
    int r = i >> 7, c4 = (i & 127) * 4;
    if (r < 512) {
        float4 x = *(const float4*)&Wv[(long)r * C + c4];
        __half* dst = g_wsv + (long)r * C;
        *(__half2*)&dst[c4]     = __halves2half2(__float2half(x.x), __float2half(x.y));
        *(__half2*)&dst[c4 + 2] = __halves2half2(__float2half(x.z), __float2half(x.w));
    } else {
        int rr = r - 512;
        const float* src = (rr < 64 ? Wq + (long)rr * C : Wk + (long)(rr - 64) * C) + c4;
        __half* dst = g_wsqk + (long)rr * KA;
        float4 x = *(const float4*)src;
        __half2 l01, l23;
        __half2 h01 = split_hi(x.x, x.y, l01);
        __half2 h23 = split_hi(x.z, x.w, l23);
        *(__half2*)&dst[c4]         = h01; *(__half2*)&dst[c4 + 2]     = h23;
        *(__half2*)&dst[C + c4]     = l01; *(__half2*)&dst[C + c4 + 2] = l23;
    }
}

// ---------------- fused HMMA projection GEMM (qk 3-prod + v 2-prod) ----------
__global__ __launch_bounds__(256, 2)
void mma_proj(const __half* __restrict__ A,
              const __half* __restrict__ wqk, const __half* __restrict__ wv,
              const float* __restrict__ bqk_, const float* __restrict__ bv_,
              __half* __restrict__ qkh, __half* __restrict__ qkl,
              __half* __restrict__ vvh) {
    extern __shared__ __align__(16) __half smp[];
    int tid = threadIdx.x, lane = tid & 31, wid = tid >> 5;
    int wm = wid >> 2, wn = wid & 3;
    int row0 = blockIdx.y * 128;
    bool isqk = (blockIdx.x == 4);
    int col0 = isqk ? 0 : blockIdx.x * 128;

    auto tile = [&](int buf, int t) -> __half* {
        return smp + (buf * 4 + t) * TILE_E;
    };

    float acc[4][4][4];
    #pragma unroll
    for (int mt = 0; mt < 4; mt++)
        #pragma unroll
        for (int nt = 0; nt < 4; nt++)
            #pragma unroll
            for (int i = 0; i < 4; i++) acc[mt][nt][i] = 0.f;

    auto load_chunk = [&](int ch, int buf) {
        int kin = ch * 32;
        #pragma unroll
        for (int j = 0; j < 2; j++) {
            int g = tid + j * 256;
            int m = g >> 2, q = g & 3;
            int gm = row0 + m;
            bool ok = gm < BP;
            const __half* abase = A + (long)(ok ? gm : 0) * KA + kin + q * 8;
            cp16(smem_u32(tile(buf, 0) + m * 40 + q * 8), abase, ok);
            cp16(smem_u32(tile(buf, 1) + m * 40 + q * 8), abase + C, ok);
            if (isqk) {
                const __half* bbase = wqk + (long)(col0 + m) * KA + kin + q * 8;
                cp16(smem_u32(tile(buf, 2) + m * 40 + q * 8), bbase, true);
                cp16(smem_u32(tile(buf, 3) + m * 40 + q * 8), bbase + C, true);
            } else {
                const __half* bbase = wv + (long)(col0 + m) * C + kin + q * 8;
                cp16(smem_u32(tile(buf, 2) + m * 40 + q * 8), bbase, true);
            }
        }
        CP_COMMIT();
    };

    load_chunk(0, 0);
    for (int ch = 0; ch < NCH; ch++) {
        int buf = ch & 1;
        if (ch + 1 < NCH) {
            load_chunk(ch + 1, buf ^ 1);
            CP_WAIT(1);
        } else {
            CP_WAIT(0);
        }
        __syncthreads();
        #pragma unroll
        for (int ks = 0; ks < 2; ks++) {
            int kk = ks * 16;
            uint32_t aH[4][4], aL[4][4], bf[4][2];
            #pragma unroll
            for (int mt = 0; mt < 4; mt++) {
                int arow = wm * 64 + mt * 16 + (lane & 15);
                int acol = kk + ((lane >> 4) << 3);
                uint32_t ad = smem_u32(tile(buf, 0) + arow * 40 + acol);
                asm volatile("ldmatrix.sync.aligned.m8n8.x4.shared.b16 {%0,%1,%2,%3}, [%4];"
                    : "=r"(aH[mt][0]), "=r"(aH[mt][1]), "=r"(aH[mt][2]), "=r"(aH[mt][3]) : "r"(ad));
                uint32_t ad2 = smem_u32(tile(buf, 1) + arow * 40 + acol);
                asm volatile("ldmatrix.sync.aligned.m8n8.x4.shared.b16 {%0,%1,%2,%3}, [%4];"
                    : "=r"(aL[mt][0]), "=r"(aL[mt][1]), "=r"(aL[mt][2]), "=r"(aL[mt][3]) : "r"(ad2));
            }
            #pragma unroll
            for (int np = 0; np < 2; np++) {
                int q = lane >> 3;
                int brow = wn * 32 + np * 16 + ((q >> 1) << 3) + (lane & 7);
                int bcol = kk + ((q & 1) << 3);
                uint32_t bd = smem_u32(tile(buf, 2) + brow * 40 + bcol);
                uint32_t r0, r1, r2, r3;
                asm volatile("ldmatrix.sync.aligned.m8n8.x4.shared.b16 {%0,%1,%2,%3}, [%4];"
                    : "=r"(r0), "=r"(r1), "=r"(r2), "=r"(r3) : "r"(bd));
                bf[np * 2][0] = r0; bf[np * 2][1] = r1;
                bf[np * 2 + 1][0] = r2; bf[np * 2 + 1][1] = r3;
            }
            #pragma unroll
            for (int mt = 0; mt < 4; mt++)
                #pragma unroll
                for (int nt = 0; nt < 4; nt++) {
                    MMA16816(acc[mt][nt], aH[mt], bf[nt]);
                    MMA16816(acc[mt][nt], aL[mt], bf[nt]);
                }
            if (isqk) {
                #pragma unroll
                for (int np = 0; np < 2; np++) {
                    int q = lane >> 3;
                    int brow = wn * 32 + np * 16 + ((q >> 1) << 3) + (lane & 7);
                    int bcol = kk + ((q & 1) << 3);
                    uint32_t bd = smem_u32(tile(buf, 3) + brow * 40 + bcol);
                    uint32_t r0, r1, r2, r3;
                    asm volatile("ldmatrix.sync.aligned.m8n8.x4.shared.b16 {%0,%1,%2,%3}, [%4];"
                        : "=r"(r0), "=r"(r1), "=r"(r2), "=r"(r3) : "r"(bd));
                    bf[np * 2][0] = r0; bf[np * 2][1] = r1;
                    bf[np * 2 + 1][0] = r2; bf[np * 2 + 1][1] = r3;
                }
                #pragma unroll
                for (int mt = 0; mt < 4; mt++)
                    #pragma unroll
                    for (int nt = 0; nt < 4; nt++)
                        MMA16816(acc[mt][nt], aH[mt], bf[nt]);
            }
        }
        __syncthreads();
    }

    const float* bias = isqk ? bqk_ : bv_;
    int Nd = isqk ? 128 : 512;
    #pragma unroll
    for (int mt = 0; mt < 4; mt++) {
        #pragma unroll
        for (int nt = 0; nt < 4; nt++) {
            int gn = col0 + wn * 32 + nt * 8 + 2 * (lane & 3);
            float b0 = bias[gn], b1 = bias[gn + 1];
            #pragma unroll
            for (int half = 0; half < 2; half++) {
                int gm = row0 + wm * 64 + mt * 16 + (lane >> 2) + half * 8;
                if (gm >= BP) continue;
                float v0 = acc[mt][nt][half * 2] + b0;
                float v1 = acc[mt][nt][half * 2 + 1] + b1;
                if (isqk) {
                    __half2 lv;
                    __half2 hv = split_hi(v0, v1, lv);
                    *(__half2*)&qkh[(long)gm * Nd + gn] = hv;
                    *(__half2*)&qkl[(long)gm * Nd + gn] = lv;
                } else {
                    *(__half2*)&vvh[(long)gm * Nd + gn] =
                        __halves2half2(__float2half(v0), __float2half(v1));
                }
            }
        }
    }
}

// ---------------- fused HMMA score kernel (fp16, 3-product) ------------------
__global__ __launch_bounds__(256, 2)
void score_mma(const __half* __restrict__ qh, const __half* __restrict__ ql,
               float* __restrict__ s) {
    extern __shared__ __align__(16) __half sms[];
    __half* Qh = sms;
    __half* Ql = sms + SC_TE;
    __half* Kh = sms + 2 * SC_TE;
    __half* Kl = sms + 3 * SC_TE;
    bool colmode = (blockIdx.x == 0);
    int b = blockIdx.z, yy = blockIdx.y;
    int tid = threadIdx.x, lane = tid & 31, wid = tid >> 5;
    int wm = wid >> 2, wn = wid & 3;
    const int rstr = colmode ? W : 1;
    long line0 = (long)b * P + (colmode ? yy : (long)yy * W);

    #pragma unroll
    for (int j = 0; j < 4; j++) {
        int idx = tid + j * 256;
        int r = idx >> 3, g8 = (idx & 7) * 8;
        bool ok = r < 97;
        long base = (line0 + (long)(ok ? r : 0) * rstr) * 128;
        cp16(smem_u32(Qh + r * 72 + g8), qh + base + g8,      ok);
        cp16(smem_u32(Ql + r * 72 + g8), ql + base + g8,      ok);
        cp16(smem_u32(Kh + r * 72 + g8), qh + base + 64 + g8, ok);
        cp16(smem_u32(Kl + r * 72 + g8), ql + base + 64 + g8, ok);
    }
    CP_COMMIT();
    CP_WAIT(0);
    __syncthreads();

    float acc[4][4][4];
    #pragma unroll
    for (int mt = 0; mt < 4; mt++)
        #pragma unroll
        for (int nt = 0; nt < 4; nt++)
            #pragma unroll
            for (int i = 0; i < 4; i++) acc[mt][nt][i] = 0.f;

    #pragma unroll
    for (int ck = 0; ck < 4; ck++) {
        int kk = ck * 16;
        uint32_t aH[4][4], aL[4][4], bH[4][2], bL[4][2];
        #pragma unroll
        for (int mt = 0; mt < 4; mt++) {
            int arow = wm * 64 + mt * 16 + (lane & 15);
            int acol = kk + ((lane >> 4) << 3);
            uint32_t ad = smem_u32(Qh + arow * 72 + acol);
            asm volatile("ldmatrix.sync.aligned.m8n8.x4.shared.b16 {%0,%1,%2,%3}, [%4];"
                : "=r"(aH[mt][0]), "=r"(aH[mt][1]), "=r"(aH[mt][2]), "=r"(aH[mt][3]) : "r"(ad));
            uint32_t ad2 = smem_u32(Ql + arow * 72 + acol);
            asm volatile("ldmatrix.sync.aligned.m8n8.x4.shared.b16 {%0,%1,%2,%3}, [%4];"
                : "=r"(aL[mt][0]), "=r"(aL[mt][1]), "=r"(aL[mt][2]), "=r"(aL[mt][3]) : "r"(ad2));
        }
        #pragma unroll
        for (int np = 0; np < 2; np++) {
            int q = lane >> 3;
            int brow = wn * 32 + np * 16 + ((q >> 1) << 3) + (lane & 7);
            int bcol = kk + ((q & 1) << 3);
            uint32_t r0, r1, r2, r3;
            uint32_t bd = smem_u32(Kh + brow * 72 + bcol);
            asm volatile("ldmatrix.sync.aligned.m8n8.x4.shared.b16 {%0,%1,%2,%3}, [%4];"
                : "=r"(r0), "=r"(r1), "=r"(r2), "=r"(r3) : "r"(bd));
            bH[np * 2][0] = r0; bH[np * 2][1] = r1;
            bH[np * 2 + 1][0] = r2; bH[np * 2 + 1][1] = r3;
            uint32_t bd2 = smem_u32(Kl + brow * 72 + bcol);
            asm volatile("ldmatrix.sync.aligned.m8n8.x4.shared.b16 {%0,%1,%2,%3}, [%4];"
                : "=r"(r0), "=r"(r1), "=r"(r2), "=r"(r3) : "r"(bd2));
            bL[np * 2][0] = r0; bL[np * 2][1] = r1;
            bL[np * 2 + 1][0] = r2; bL[np * 2 + 1][1] = r3;
        }
        #pragma unroll
        for (int mt = 0; mt < 4; mt++)
            #pragma unroll
            for (int nt = 0; nt < 4; nt++) {
                MMA16816(acc[mt][nt], aH[mt], bH[nt]);
                MMA16816(acc[mt][nt], aL[mt], bH[nt]);
                MMA16816(acc[mt][nt], aH[mt], bL[nt]);
            }
    }

    #pragma unroll
    for (int mt = 0; mt < 4; mt++) {
        #pragma unroll
        for (int nt = 0; nt < 4; nt++) {
            int gn = wn * 32 + nt * 8 + 2 * (lane & 3);
            #pragma unroll
            for (int half = 0; half < 2; half++) {
                int r = wm * 64 + mt * 16 + (lane >> 2) + half * 8;
                if (r >= 97) continue;
                float* outp = s + (line0 + (long)r * rstr) * S + (colmode ? 0 : 97);
                float v0 = acc[mt][nt][half * 2];
                float v1 = acc[mt][nt][half * 2 + 1];
                if (colmode && r == gn)     v0 += NEG_INF;
                if (colmode && r == gn + 1) v1 += NEG_INF;
                if (gn < 97)     outp[gn]     = v0;
                if (gn + 1 < 97) outp[gn + 1] = v1;
            }
        }
    }
}

// ---------------- softmax: f32 scores -> fp16 attention (hi only) ------------
__global__ __launch_bounds__(256)
void softmax194(const float* __restrict__ s, __half* __restrict__ sh) {
    long row = (long)blockIdx.x * 8 + (threadIdx.x >> 5);
    int lane = threadIdx.x & 31;
    const float* r = s + row * S;
    float v[7];
    float m = -3.0e38f;
    #pragma unroll
    for (int t = 0; t < 7; t++) {
        int idx = lane + 32 * t;
        v[t] = (idx < S) ? r[idx] : -3.0e38f;
        m = fmaxf(m, v[t]);
    }
    #pragma unroll
    for (int o = 16; o > 0; o >>= 1) m = fmaxf(m, __shfl_xor_sync(0xffffffffu, m, o));
    float sum = 0.f;
    #pragma unroll
    for (int t = 0; t < 7; t++) { v[t] = __expf(v[t] - m); sum += v[t]; }
    #pragma unroll
    for (int o = 16; o > 0; o >>= 1) sum += __shfl_xor_sync(0xffffffffu, sum, o);
    float inv = 1.0f / sum;
    __half* shr = sh + row * SP;
    #pragma unroll
    for (int t = 0; t < 7; t++) {
        int idx = lane + 32 * t;
        if (idx < S) {
            float val = v[t] * inv;
            int o = idx < 97 ? idx : OFFW + (idx - 97);
            shr[o] = __float2half(val);
        }
    }
}

// ---------------- HMMA apply: A single fp16, V single fp16, 1 product --------
template<bool COLMODE>
__global__ __launch_bounds__(256, 2)
void apply_mma(const __half* __restrict__ sh,
               const __half* __restrict__ vh,
               float* __restrict__ y, const float* __restrict__ x,
               const float* __restrict__ gamma, __half* __restrict__ xs) {
    extern __shared__ __align__(16) __half sma[];
    __half* Ah = sma;                 // [2][128][40]
    __half* Vh = sma + 2 * APT;       // [2][32][136]
    int b = blockIdx.z, yy = blockIdx.y, c0 = blockIdx.x * 128;
    int tid = threadIdx.x, lane = tid & 31, wid = tid >> 5;
    int wm = wid >> 2, wn = wid & 3;
    const int rstr = COLMODE ? W : 1;
    long line0 = (long)b * P + (COLMODE ? yy : (long)yy * W);
    const int off = COLMODE ? 0 : OFFW;

    float acc[4][4][4];
    #pragma unroll
    for (int mt = 0; mt < 4; mt++)
        #pragma unroll
        for (int nt = 0; nt < 4; nt++)
            #pragma unroll
            for (int i = 0; i < 4; i++) acc[mt][nt][i] = 0.f;

    auto load_chunk = [&](int ch, int buf) {
        int g0 = ch * 32;
        #pragma unroll
        for (int j = 0; j < 2; j++) {
            int idx = tid + j * 256;
            int r = idx >> 2, q = idx & 3;
            int gg = g0 + q * 8;
            int ab = (r < 97 && gg < 97) ? min(97 - gg, 8) * 2 : 0;
            long rowoff = (line0 + (long)(r < 97 ? r : 0) * rstr) * SP + off + (gg < 97 ? gg : 0);
            cp16v(smem_u32(Ah + buf * APT + r * 40 + q * 8), sh + rowoff, ab);
        }
        #pragma unroll
        for (int j = 0; j < 2; j++) {
            int idx = tid + j * 256;
            int g = idx >> 4, c8 = (idx & 15) * 8;
            int gabs = g0 + g;
            int vb = (gabs < 97) ? 16 : 0;
            long nk = (line0 + (long)(gabs < 97 ? gabs : 0) * rstr) * C + c0 + c8;
            cp16v(smem_u32(Vh + buf * VPT + g * 136 + c8), vh + nk, vb);
        }
        CP_COMMIT();
    };

    load_chunk(0, 0);
    for (int ch = 0; ch < 4; ch++) {
        int cur = ch & 1;
        if (ch + 1 < 4) {
            load_chunk(ch + 1, cur ^ 1);
            CP_WAIT(1);
        } else {
            CP_WAIT(0);
        }
        __syncthreads();
        #pragma unroll
        for (int ks = 0; ks < 2; ks++) {
            int kk = ks * 16;
            uint32_t aH[4][4], bf[4][2];
            #pragma unroll
            for (int mt = 0; mt < 4; mt++) {
                int arow = wm * 64 + mt * 16 + (lane & 15);
                int acol = kk + ((lane >> 4) << 3);
                uint32_t ad = smem_u32(Ah + cur * APT + arow * 40 + acol);
                asm volatile("ldmatrix.sync.aligned.m8n8.x4.shared.b16 {%0,%1,%2,%3}, [%4];"
                    : "=r"(aH[mt][0]), "=r"(aH[mt][1]), "=r"(aH[mt][2]), "=r"(aH[mt][3]) : "r"(ad));
            }
            #pragma unroll
            for (int np = 0; np < 2; np++) {
                int q = lane >> 3;
                int krow = kk + ((q & 1) << 3) + (lane & 7);
                int ncol = wn * 32 + np * 16 + ((q >> 1) << 3);
                uint32_t r0, r1, r2, r3;
                uint32_t bd = smem_u32(Vh + cur * VPT + krow * 136 + ncol);
                asm volatile("ldmatrix.sync.aligned.m8n8.x4.trans.shared.b16 {%0,%1,%2,%3}, [%4];"
                    : "=r"(r0), "=r"(r1), "=r"(r2), "=r"(r3) : "r"(bd));
                bf[np * 2][0] = r0; bf[np * 2][1] = r1;
                bf[np * 2 + 1][0] = r2; bf[np * 2 + 1][1] = r3;
            }
            #pragma unroll
            for (int mt = 0; mt < 4; mt++)
                #pragma unroll
                for (int nt = 0; nt < 4; nt++)
                    MMA16816(acc[mt][nt], aH[mt], bf[nt]);
        }
        __syncthreads();
    }

    float gmv = COLMODE ? 0.f : __ldg(gamma);
    #pragma unroll
    for (int mt = 0; mt < 4; mt++) {
        #pragma unroll
        for (int nt = 0; nt < 4; nt++) {
            int gn = c0 + wn * 32 + nt * 8 + 2 * (lane & 3);
            #pragma unroll
            for (int half = 0; half < 2; half++) {
                int r = wm * 64 + mt * 16 + (lane >> 2) + half * 8;
                if (r >= 97) continue;
                long node = line0 + (long)r * rstr;
                long addr = node * C + gn;
                float a0 = acc[mt][nt][half * 2], a1 = acc[mt][nt][half * 2 + 1];
                if (COLMODE) {
                    float2 o; o.x = a0; o.y = a1;
                    *(float2*)&y[addr] = o;
                } else {
                    float2 p = *(const float2*)&y[addr];
                    float2 xx = *(const float2*)&x[addr];
                    float2 o;
                    o.x = gmv * (p.x + a0) + xx.x;
                    o.y = gmv * (p.y + a1) + xx.y;
                    *(float2*)&y[addr] = o;
                    if (xs) {
                        __half2 lv;
                        __half2 hv = split_hi(o.x, o.y, lv);
                        *(__half2*)&xs[node * KA + gn]     = hv;
                        *(__half2*)&xs[node * KA + C + gn] = lv;
                    }
                }
            }
        }
    }
}

// ---------------- launch -----------------------------------------------------
extern "C" void kernel_launch(void* const* d_in, const int* in_sizes, int n_in,
                              void* d_out, int out_size) {
    const float* x     = (const float*)d_in[0];
    const float* Wq    = (const float*)d_in[1];
    const float* bq    = (const float*)d_in[2];
    const float* Wk    = (const float*)d_in[3];
    const float* bk    = (const float*)d_in[4];
    const float* Wv    = (const float*)d_in[5];
    const float* bv    = (const float*)d_in[6];
    const float* gamma = (const float*)d_in[7];
    float* out = (float*)d_out;

    float *xT, *yT, *sp, *bqk;
    __half *xs, *wsv, *wsqk, *sh, *vh, *qkh, *qkl;
    cudaGetSymbolAddress((void**)&xT,  g_xT);
    cudaGetSymbolAddress((void**)&yT,  g_yT);
    cudaGetSymbolAddress((void**)&sp,  g_s);
    cudaGetSymbolAddress((void**)&xs,   g_xs);
    cudaGetSymbolAddress((void**)&wsv,  g_wsv);
    cudaGetSymbolAddress((void**)&wsqk, g_wsqk);
    cudaGetSymbolAddress((void**)&bqk,  g_bqk);
    cudaGetSymbolAddress((void**)&sh,  g_sh);
    cudaGetSymbolAddress((void**)&vh,  g_vh);
    cudaGetSymbolAddress((void**)&qkh, g_qkh);
    cudaGetSymbolAddress((void**)&qkl, g_qkl);

    cudaFuncSetAttribute(mma_proj,  cudaFuncAttributeMaxDynamicSharedMemorySize, SMEM_PROJ);
    cudaFuncSetAttribute(score_mma, cudaFuncAttributeMaxDynamicSharedMemorySize, SMEM_SCORE);
    cudaFuncSetAttribute(apply_mma<true >, cudaFuncAttributeMaxDynamicSharedMemorySize, SMEM_APPLY);
    cudaFuncSetAttribute(apply_mma<false>, cudaFuncAttributeMaxDynamicSharedMemorySize, SMEM_APPLY);

    dim3 tgrid((P + 31) / 32, C / 32, B), tthr(32, 8);
    transpose_in<<<tgrid, tthr>>>(x, xT, xs);
    prep_w<<<320, 256>>>(Wq, Wk, Wv, bq, bk);

    for (int it = 0; it < 2; it++) {
        const float* X = it ? yT : xT;
        float*       Y = it ? xT : yT;
        mma_proj<<<dim3(5, MBLK), 256, SMEM_PROJ>>>(xs, wsqk, wsv, bqk, bv, qkh, qkl, vh);
        score_mma<<<dim3(2, W, B), 256, SMEM_SCORE>>>(qkh, qkl, sp);
        softmax194<<<P, 256>>>(sp, sh);
        apply_mma<true ><<<dim3(4, W, B), 256, SMEM_APPLY>>>(sh, vh, Y, X, gamma, nullptr);
        apply_mma<false><<<dim3(4, H, B), 256, SMEM_APPLY>>>(sh, vh, Y, X, gamma, it == 0 ? xs : nullptr);
    }

    transpose_out<<<tgrid, tthr>>>(xT, out);
}